// round 1
// baseline (speedup 1.0000x reference)
#include <cuda_runtime.h>
#include <math.h>

#define B_   64
#define N_   36
#define ROWS 2304      // B_*N_
#define DF   2048
#define DATT 512
#define DC   8

// Scratch (static device allocations are allowed; runtime allocs are not)
__device__ float g_tmp1[ROWS * DF];   // qe@Wq, then fused (after elemmul)
__device__ float g_tmp2[ROWS * DF];   // obj@Wo
__device__ float g_ra[ROWS * DF];
__device__ float g_rb[ROWS * DF];
__device__ float g_ba[ROWS * DF];
__device__ float g_bb[ROWS * DF];

// ---------------------------------------------------------------------------
// Classic 128x128x8 register-blocked SGEMM, 256 threads, 8x8 micro-tile.
// Assumes M%128==0, N%128==0, K%8==0 (true for all calls here).
// ---------------------------------------------------------------------------
__global__ __launch_bounds__(256, 2)
void sgemm128(const float* __restrict__ A, const float* __restrict__ B,
              float* __restrict__ C, int M, int N, int K) {
    __shared__ float As[8][132];   // transposed A tile, padded vs STS conflicts
    __shared__ float Bs[8][128];

    const int tid = threadIdx.x;
    const int tx  = tid & 15;
    const int ty  = tid >> 4;
    const int rowBase = blockIdx.y * 128;
    const int colBase = blockIdx.x * 128;

    const int arow = tid >> 1;
    const int acol = (tid & 1) * 4;
    const int brow = tid >> 5;
    const int bcol = (tid & 31) * 4;

    const float* Ap = A + (size_t)(rowBase + arow) * K + acol;
    const float* Bp = B + (size_t)brow * N + colBase + bcol;

    float4 an = *(const float4*)Ap;
    float4 bn = *(const float4*)Bp;

    float acc[8][8];
#pragma unroll
    for (int i = 0; i < 8; i++)
#pragma unroll
        for (int j = 0; j < 8; j++) acc[i][j] = 0.f;

    for (int k0 = 0; k0 < K; k0 += 8) {
        As[acol + 0][arow] = an.x;
        As[acol + 1][arow] = an.y;
        As[acol + 2][arow] = an.z;
        As[acol + 3][arow] = an.w;
        *(float4*)&Bs[brow][bcol] = bn;
        __syncthreads();
        if (k0 + 8 < K) {
            an = *(const float4*)(Ap + k0 + 8);
            bn = *(const float4*)(Bp + (size_t)(k0 + 8) * N);
        }
#pragma unroll
        for (int kk = 0; kk < 8; kk++) {
            // split-column layout: {t*4..t*4+3} U {64+t*4..} -> conflict-free LDS.128
            float4 a0 = *(float4*)&As[kk][ty * 4];
            float4 a1 = *(float4*)&As[kk][64 + ty * 4];
            float4 b0 = *(float4*)&Bs[kk][tx * 4];
            float4 b1 = *(float4*)&Bs[kk][64 + tx * 4];
            float ar[8] = {a0.x, a0.y, a0.z, a0.w, a1.x, a1.y, a1.z, a1.w};
            float br[8] = {b0.x, b0.y, b0.z, b0.w, b1.x, b1.y, b1.z, b1.w};
#pragma unroll
            for (int i = 0; i < 8; i++)
#pragma unroll
                for (int j = 0; j < 8; j++) acc[i][j] += ar[i] * br[j];
        }
        __syncthreads();
    }

#pragma unroll
    for (int i = 0; i < 8; i++) {
        int r = rowBase + ((i < 4) ? (ty * 4 + i) : (64 + ty * 4 + (i - 4)));
        float4 v0 = make_float4(acc[i][0], acc[i][1], acc[i][2], acc[i][3]);
        float4 v1 = make_float4(acc[i][4], acc[i][5], acc[i][6], acc[i][7]);
        *(float4*)&C[(size_t)r * N + colBase + tx * 4]      = v0;
        *(float4*)&C[(size_t)r * N + colBase + 64 + tx * 4] = v1;
    }
}

// fused = tmp1 * tmp2 (in place into tmp1)
__global__ void elemmul(float* __restrict__ a, const float* __restrict__ b, int n4) {
    int i = blockIdx.x * blockDim.x + threadIdx.x;
    if (i < n4) {
        float4 x = ((float4*)a)[i];
        float4 y = ((const float4*)b)[i];
        x.x *= y.x; x.y *= y.y; x.z *= y.z; x.w *= y.w;
        ((float4*)a)[i] = x;
    }
}

// ba = boxes @ Wba, bb = boxes @ Wbb  (K = 4, trivial)
__global__ void boxproj(const float* __restrict__ boxes,
                        const float* __restrict__ Wba, const float* __restrict__ Wbb,
                        float* __restrict__ ba, float* __restrict__ bb) {
    int idx = blockIdx.x * blockDim.x + threadIdx.x;
    if (idx >= ROWS * (DF / 4)) return;
    int r  = idx / (DF / 4);
    int dq = (idx % (DF / 4)) * 4;
    float4 bx = *(const float4*)&boxes[r * 4];
    float c[4] = {bx.x, bx.y, bx.z, bx.w};
    float4 sa = make_float4(0.f, 0.f, 0.f, 0.f);
    float4 sb = make_float4(0.f, 0.f, 0.f, 0.f);
#pragma unroll
    for (int cc = 0; cc < 4; cc++) {
        float4 wa = *(const float4*)&Wba[cc * DF + dq];
        float4 wb = *(const float4*)&Wbb[cc * DF + dq];
        sa.x += c[cc] * wa.x; sa.y += c[cc] * wa.y; sa.z += c[cc] * wa.z; sa.w += c[cc] * wa.w;
        sb.x += c[cc] * wb.x; sb.y += c[cc] * wb.y; sb.z += c[cc] * wb.z; sb.w += c[cc] * wb.w;
    }
    *(float4*)&ba[(size_t)r * DF + dq] = sa;
    *(float4*)&bb[(size_t)r * DF + dq] = sb;
}

// ---------------------------------------------------------------------------
// Fused relation-attention: one CTA per (b, i).
//   G[j,d]   = ra_i[d]*rb[b,j,d] + ba_i[d]*bb[b,j,d]   (built on the fly)
//   R[j,k]   = sum_d G[j,d] * W0[d,k]                  (the 174 GFLOP GEMM)
//   score[j] = sum_k W1[k] * tanh(R[j,k] + b0[k])      (b1 cancels in softmax)
//   att      = softmax_j(score)
//   out[i,:] = obj[i,:] + fused[i,:] + ra_i .* (att@rb) + ba_i .* (att@bb)
// Thread layout: jt = tid>>6 (4), kt = tid&63 (64); thread owns 9 j's x 8 k's.
// k ownership split {kt*4..+3} U {256+kt*4..+3} -> conflict-free LDS.128 on W0_s.
// ---------------------------------------------------------------------------
__global__ __launch_bounds__(256, 2)
void relattn(const float* __restrict__ ra, const float* __restrict__ rb,
             const float* __restrict__ ba, const float* __restrict__ bb,
             const float* __restrict__ W0, const float* __restrict__ b0,
             const float* __restrict__ W1,
             const float* __restrict__ obj, const float* __restrict__ fus,
             float* __restrict__ out) {
    __shared__ float ra_s[DF];            // 8 KB
    __shared__ float ba_s[DF];            // 8 KB
    __shared__ float W0_s[DC][DATT];      // 16 KB
    __shared__ float Gs[N_][DC];          // 1.1 KB
    __shared__ float wb_s[DATT];          // W1
    __shared__ float b0_s[DATT];
    __shared__ float warp_s[8][9];        // deterministic score partials
    __shared__ float sc_s[N_];
    __shared__ float att_s[N_];

    const int tid = threadIdx.x;
    const int bi  = blockIdx.x;           // b*N_ + i
    const int b   = bi / N_;
    const int jt  = tid >> 6;             // 0..3
    const int kt  = tid & 63;             // 0..63

    const float* raRow = ra + (size_t)bi * DF;
    const float* baRow = ba + (size_t)bi * DF;
#pragma unroll
    for (int d = tid * 4; d < DF; d += 1024) {
        *(float4*)&ra_s[d] = *(const float4*)&raRow[d];
        *(float4*)&ba_s[d] = *(const float4*)&baRow[d];
    }
    for (int k = tid; k < DATT; k += 256) {
        wb_s[k] = W1[k];
        b0_s[k] = b0[k];
    }
    __syncthreads();

    float acc[9][8];
#pragma unroll
    for (int jj = 0; jj < 9; jj++)
#pragma unroll
        for (int kk = 0; kk < 8; kk++) acc[jj][kk] = 0.f;

    const float* rbB = rb + (size_t)b * N_ * DF;
    const float* bbB = bb + (size_t)b * N_ * DF;

    for (int d0 = 0; d0 < DF; d0 += DC) {
        // stage W0 chunk [DC][DATT]: 1024 float4, 4 per thread, coalesced
#pragma unroll
        for (int v = 0; v < 4; v++) {
            int idx = tid + v * 256;
            int dd  = idx >> 7;
            int kq  = (idx & 127) * 4;
            *(float4*)&W0_s[dd][kq] =
                *(const float4*)&W0[(size_t)(d0 + dd) * DATT + kq];
        }
        // stage G chunk [36][DC]: 72 float4
        if (tid < 72) {
            int j = tid >> 1;
            int d = d0 + (tid & 1) * 4;
            float4 r4 = *(const float4*)&rbB[(size_t)j * DF + d];
            float4 q4 = *(const float4*)&bbB[(size_t)j * DF + d];
            float4 u4 = *(float4*)&ra_s[d];
            float4 v4 = *(float4*)&ba_s[d];
            float4 g;
            g.x = u4.x * r4.x + v4.x * q4.x;
            g.y = u4.y * r4.y + v4.y * q4.y;
            g.z = u4.z * r4.z + v4.z * q4.z;
            g.w = u4.w * r4.w + v4.w * q4.w;
            *(float4*)&Gs[j][(tid & 1) * 4] = g;
        }
        __syncthreads();
#pragma unroll
        for (int dd = 0; dd < DC; dd++) {
            float4 w0 = *(float4*)&W0_s[dd][kt * 4];
            float4 w1 = *(float4*)&W0_s[dd][256 + kt * 4];
#pragma unroll
            for (int jj = 0; jj < 9; jj++) {
                float g = Gs[jt + jj * 4][dd];   // warp-broadcast
                acc[jj][0] += g * w0.x;
                acc[jj][1] += g * w0.y;
                acc[jj][2] += g * w0.z;
                acc[jj][3] += g * w0.w;
                acc[jj][4] += g * w1.x;
                acc[jj][5] += g * w1.y;
                acc[jj][6] += g * w1.z;
                acc[jj][7] += g * w1.w;
            }
        }
        __syncthreads();
    }

    // per-thread score partials -> deterministic warp reduce
    const int kA = kt * 4;
    const int kB = 256 + kt * 4;
#pragma unroll
    for (int jj = 0; jj < 9; jj++) {
        float s = 0.f;
        s += wb_s[kA + 0] * tanhf(acc[jj][0] + b0_s[kA + 0]);
        s += wb_s[kA + 1] * tanhf(acc[jj][1] + b0_s[kA + 1]);
        s += wb_s[kA + 2] * tanhf(acc[jj][2] + b0_s[kA + 2]);
        s += wb_s[kA + 3] * tanhf(acc[jj][3] + b0_s[kA + 3]);
        s += wb_s[kB + 0] * tanhf(acc[jj][4] + b0_s[kB + 0]);
        s += wb_s[kB + 1] * tanhf(acc[jj][5] + b0_s[kB + 1]);
        s += wb_s[kB + 2] * tanhf(acc[jj][6] + b0_s[kB + 2]);
        s += wb_s[kB + 3] * tanhf(acc[jj][7] + b0_s[kB + 3]);
#pragma unroll
        for (int off = 16; off > 0; off >>= 1)
            s += __shfl_xor_sync(0xffffffffu, s, off);
        if ((tid & 31) == 0) warp_s[tid >> 5][jj] = s;   // all lanes of a warp share j
    }
    __syncthreads();
    if (tid < N_) {           // j = (j&3) + 4*(j>>2); warps 2*jt, 2*jt+1 hold partials
        int j4  = tid & 3;
        int jjj = tid >> 2;
        sc_s[tid] = warp_s[2 * j4][jjj] + warp_s[2 * j4 + 1][jjj];
    }
    __syncthreads();
    if (tid == 0) {           // softmax over 36 values, serial, deterministic
        float m = sc_s[0];
        for (int j = 1; j < N_; j++) m = fmaxf(m, sc_s[j]);
        float sum = 0.f;
        for (int j = 0; j < N_; j++) {
            float e = expf(sc_s[j] - m);
            att_s[j] = e;
            sum += e;
        }
        float inv = 1.f / sum;
        for (int j = 0; j < N_; j++) att_s[j] *= inv;
    }
    __syncthreads();

    // e_hat + residuals + output
    const float* objRow = obj + (size_t)bi * DF;
    const float* fusRow = fus + (size_t)bi * DF;
    float* outRow = out + (size_t)bi * DF;
    for (int d = tid * 4; d < DF; d += 1024) {
        float srx = 0.f, sry = 0.f, srz = 0.f, srw = 0.f;
        float sbx = 0.f, sby = 0.f, sbz = 0.f, sbw = 0.f;
#pragma unroll 6
        for (int j = 0; j < N_; j++) {
            float a = att_s[j];
            float4 r4 = *(const float4*)&rbB[(size_t)j * DF + d];
            float4 q4 = *(const float4*)&bbB[(size_t)j * DF + d];
            srx += a * r4.x; sry += a * r4.y; srz += a * r4.z; srw += a * r4.w;
            sbx += a * q4.x; sby += a * q4.y; sbz += a * q4.z; sbw += a * q4.w;
        }
        float4 u4 = *(float4*)&ra_s[d];
        float4 v4 = *(float4*)&ba_s[d];
        float4 o4 = *(const float4*)&objRow[d];
        float4 f4 = *(const float4*)&fusRow[d];
        float4 res;
        res.x = o4.x + f4.x + u4.x * srx + v4.x * sbx;
        res.y = o4.y + f4.y + u4.y * sry + v4.y * sby;
        res.z = o4.z + f4.z + u4.z * srz + v4.z * sbz;
        res.w = o4.w + f4.w + u4.w * srw + v4.w * sbw;
        *(float4*)&outRow[d] = res;
    }
}

extern "C" void kernel_launch(void* const* d_in, const int* in_sizes, int n_in,
                              void* d_out, int out_size) {
    const float* qe    = (const float*)d_in[0];   // [2304, 2048]
    const float* obj   = (const float*)d_in[1];   // [64, 36, 2048]
    const float* boxes = (const float*)d_in[2];   // [64, 36, 4]
    const float* Wq    = (const float*)d_in[3];
    const float* Wo    = (const float*)d_in[4];
    const float* Wfa   = (const float*)d_in[5];
    const float* Wfb   = (const float*)d_in[6];
    const float* Wba   = (const float*)d_in[7];
    const float* Wbb   = (const float*)d_in[8];
    const float* W0    = (const float*)d_in[9];
    const float* b0    = (const float*)d_in[10];
    const float* W1    = (const float*)d_in[11];
    // d_in[12] = b1 (cancels in softmax), d_in[13..] = scalars (hardcoded)
    float* out = (float*)d_out;

    float *tmp1, *tmp2, *ra, *rb, *ba, *bb;
    cudaGetSymbolAddress((void**)&tmp1, g_tmp1);
    cudaGetSymbolAddress((void**)&tmp2, g_tmp2);
    cudaGetSymbolAddress((void**)&ra,   g_ra);
    cudaGetSymbolAddress((void**)&rb,   g_rb);
    cudaGetSymbolAddress((void**)&ba,   g_ba);
    cudaGetSymbolAddress((void**)&bb,   g_bb);

    dim3 gg(DF / 128, ROWS / 128);   // (16, 18)
    int n4 = ROWS * DF / 4;

    sgemm128<<<gg, 256>>>(qe,   Wq,  tmp1, ROWS, DF, DF);
    sgemm128<<<gg, 256>>>(obj,  Wo,  tmp2, ROWS, DF, DF);
    elemmul <<<(n4 + 255) / 256, 256>>>(tmp1, tmp2, n4);     // tmp1 = fused
    sgemm128<<<gg, 256>>>(tmp1, Wfa, ra,   ROWS, DF, DF);
    sgemm128<<<gg, 256>>>(tmp1, Wfb, rb,   ROWS, DF, DF);
    boxproj <<<(n4 + 255) / 256, 256>>>(boxes, Wba, Wbb, ba, bb);
    relattn <<<ROWS, 256>>>(ra, rb, ba, bb, W0, b0, W1, obj, tmp1, out);
}

// round 2
// speedup vs baseline: 1.6435x; 1.6435x over previous
#include <cuda_runtime.h>
#include <math.h>

#define B_   64
#define N_   36
#define ROWS 2304      // B_*N_
#define DF   2048
#define DATT 512
#define DC   8

// Scratch (static device allocations are allowed; runtime allocs are not)
__device__ float g_tmp1[ROWS * DF];   // qe@Wq, then fused (after elemmul)
__device__ float g_tmp2[ROWS * DF];   // obj@Wo
__device__ float g_ra[ROWS * DF];
__device__ float g_rb[ROWS * DF];
__device__ float g_ba[ROWS * DF];
__device__ float g_bb[ROWS * DF];

// ---------------------------------------------------------------------------
// Classic 128x128x8 register-blocked SGEMM, 256 threads, 8x8 micro-tile.
// Assumes M%128==0, N%128==0, K%8==0 (true for all calls here).
// ---------------------------------------------------------------------------
__global__ __launch_bounds__(256, 2)
void sgemm128(const float* __restrict__ A, const float* __restrict__ B,
              float* __restrict__ C, int M, int N, int K) {
    __shared__ float As[8][132];   // transposed A tile, padded vs STS conflicts
    __shared__ float Bs[8][128];

    const int tid = threadIdx.x;
    const int tx  = tid & 15;
    const int ty  = tid >> 4;
    const int rowBase = blockIdx.y * 128;
    const int colBase = blockIdx.x * 128;

    const int arow = tid >> 1;
    const int acol = (tid & 1) * 4;
    const int brow = tid >> 5;
    const int bcol = (tid & 31) * 4;

    const float* Ap = A + (size_t)(rowBase + arow) * K + acol;
    const float* Bp = B + (size_t)brow * N + colBase + bcol;

    float4 an = *(const float4*)Ap;
    float4 bn = *(const float4*)Bp;

    float acc[8][8];
#pragma unroll
    for (int i = 0; i < 8; i++)
#pragma unroll
        for (int j = 0; j < 8; j++) acc[i][j] = 0.f;

    for (int k0 = 0; k0 < K; k0 += 8) {
        As[acol + 0][arow] = an.x;
        As[acol + 1][arow] = an.y;
        As[acol + 2][arow] = an.z;
        As[acol + 3][arow] = an.w;
        *(float4*)&Bs[brow][bcol] = bn;
        __syncthreads();
        if (k0 + 8 < K) {
            an = *(const float4*)(Ap + k0 + 8);
            bn = *(const float4*)(Bp + (size_t)(k0 + 8) * N);
        }
#pragma unroll
        for (int kk = 0; kk < 8; kk++) {
            // split-column layout: {t*4..t*4+3} U {64+t*4..} -> conflict-free LDS.128
            float4 a0 = *(float4*)&As[kk][ty * 4];
            float4 a1 = *(float4*)&As[kk][64 + ty * 4];
            float4 b0 = *(float4*)&Bs[kk][tx * 4];
            float4 b1 = *(float4*)&Bs[kk][64 + tx * 4];
            float ar[8] = {a0.x, a0.y, a0.z, a0.w, a1.x, a1.y, a1.z, a1.w};
            float br[8] = {b0.x, b0.y, b0.z, b0.w, b1.x, b1.y, b1.z, b1.w};
#pragma unroll
            for (int i = 0; i < 8; i++)
#pragma unroll
                for (int j = 0; j < 8; j++) acc[i][j] += ar[i] * br[j];
        }
        __syncthreads();
    }

#pragma unroll
    for (int i = 0; i < 8; i++) {
        int r = rowBase + ((i < 4) ? (ty * 4 + i) : (64 + ty * 4 + (i - 4)));
        float4 v0 = make_float4(acc[i][0], acc[i][1], acc[i][2], acc[i][3]);
        float4 v1 = make_float4(acc[i][4], acc[i][5], acc[i][6], acc[i][7]);
        *(float4*)&C[(size_t)r * N + colBase + tx * 4]      = v0;
        *(float4*)&C[(size_t)r * N + colBase + 64 + tx * 4] = v1;
    }
}

// fused = tmp1 * tmp2 (in place into tmp1)
__global__ void elemmul(float* __restrict__ a, const float* __restrict__ b, int n4) {
    int i = blockIdx.x * blockDim.x + threadIdx.x;
    if (i < n4) {
        float4 x = ((float4*)a)[i];
        float4 y = ((const float4*)b)[i];
        x.x *= y.x; x.y *= y.y; x.z *= y.z; x.w *= y.w;
        ((float4*)a)[i] = x;
    }
}

// ba = boxes @ Wba, bb = boxes @ Wbb  (K = 4, trivial)
__global__ void boxproj(const float* __restrict__ boxes,
                        const float* __restrict__ Wba, const float* __restrict__ Wbb,
                        float* __restrict__ ba, float* __restrict__ bb) {
    int idx = blockIdx.x * blockDim.x + threadIdx.x;
    if (idx >= ROWS * (DF / 4)) return;
    int r  = idx / (DF / 4);
    int dq = (idx % (DF / 4)) * 4;
    float4 bx = *(const float4*)&boxes[r * 4];
    float c[4] = {bx.x, bx.y, bx.z, bx.w};
    float4 sa = make_float4(0.f, 0.f, 0.f, 0.f);
    float4 sb = make_float4(0.f, 0.f, 0.f, 0.f);
#pragma unroll
    for (int cc = 0; cc < 4; cc++) {
        float4 wa = *(const float4*)&Wba[cc * DF + dq];
        float4 wb = *(const float4*)&Wbb[cc * DF + dq];
        sa.x += c[cc] * wa.x; sa.y += c[cc] * wa.y; sa.z += c[cc] * wa.z; sa.w += c[cc] * wa.w;
        sb.x += c[cc] * wb.x; sb.y += c[cc] * wb.y; sb.z += c[cc] * wb.z; sb.w += c[cc] * wb.w;
    }
    *(float4*)&ba[(size_t)r * DF + dq] = sa;
    *(float4*)&bb[(size_t)r * DF + dq] = sb;
}

// ---------------------------------------------------------------------------
// Fused relation-attention: one CTA per (b, i).
//   G[j,d]   = ra_i[d]*rb[b,j,d] + ba_i[d]*bb[b,j,d]   (built on the fly)
//   R[j,k]   = sum_d G[j,d] * W0[d,k]                  (the 174 GFLOP GEMM)
//   score[j] = sum_k W1[k] * tanh(R[j,k] + b0[k])      (b1 cancels in softmax)
//   att      = softmax_j(score)
//   out[i,:] = obj[i,:] + fused[i,:] + ra_i .* (att@rb) + ba_i .* (att@bb)
// Thread layout: jt = tid>>6 (4), kt = tid&63 (64); thread owns 9 j's x 8 k's.
// k ownership split {kt*4..+3} U {256+kt*4..+3} -> conflict-free LDS.128 on W0_s.
// ---------------------------------------------------------------------------
__global__ __launch_bounds__(256, 2)
void relattn(const float* __restrict__ ra, const float* __restrict__ rb,
             const float* __restrict__ ba, const float* __restrict__ bb,
             const float* __restrict__ W0, const float* __restrict__ b0,
             const float* __restrict__ W1,
             const float* __restrict__ obj, const float* __restrict__ fus,
             float* __restrict__ out) {
    __shared__ float ra_s[DF];            // 8 KB
    __shared__ float ba_s[DF];            // 8 KB
    __shared__ float W0_s[DC][DATT];      // 16 KB
    __shared__ float Gs[N_][DC];          // 1.1 KB
    __shared__ float wb_s[DATT];          // W1
    __shared__ float b0_s[DATT];
    __shared__ float warp_s[8][9];        // deterministic score partials
    __shared__ float sc_s[N_];
    __shared__ float att_s[N_];

    const int tid = threadIdx.x;
    const int bi  = blockIdx.x;           // b*N_ + i
    const int b   = bi / N_;
    const int jt  = tid >> 6;             // 0..3
    const int kt  = tid & 63;             // 0..63

    const float* raRow = ra + (size_t)bi * DF;
    const float* baRow = ba + (size_t)bi * DF;
#pragma unroll
    for (int d = tid * 4; d < DF; d += 1024) {
        *(float4*)&ra_s[d] = *(const float4*)&raRow[d];
        *(float4*)&ba_s[d] = *(const float4*)&baRow[d];
    }
    for (int k = tid; k < DATT; k += 256) {
        wb_s[k] = W1[k];
        b0_s[k] = b0[k];
    }
    __syncthreads();

    float acc[9][8];
#pragma unroll
    for (int jj = 0; jj < 9; jj++)
#pragma unroll
        for (int kk = 0; kk < 8; kk++) acc[jj][kk] = 0.f;

    const float* rbB = rb + (size_t)b * N_ * DF;
    const float* bbB = bb + (size_t)b * N_ * DF;

    for (int d0 = 0; d0 < DF; d0 += DC) {
        // stage W0 chunk [DC][DATT]: 1024 float4, 4 per thread, coalesced
#pragma unroll
        for (int v = 0; v < 4; v++) {
            int idx = tid + v * 256;
            int dd  = idx >> 7;
            int kq  = (idx & 127) * 4;
            *(float4*)&W0_s[dd][kq] =
                *(const float4*)&W0[(size_t)(d0 + dd) * DATT + kq];
        }
        // stage G chunk [36][DC]: 72 float4
        if (tid < 72) {
            int j = tid >> 1;
            int d = d0 + (tid & 1) * 4;
            float4 r4 = *(const float4*)&rbB[(size_t)j * DF + d];
            float4 q4 = *(const float4*)&bbB[(size_t)j * DF + d];
            float4 u4 = *(float4*)&ra_s[d];
            float4 v4 = *(float4*)&ba_s[d];
            float4 g;
            g.x = u4.x * r4.x + v4.x * q4.x;
            g.y = u4.y * r4.y + v4.y * q4.y;
            g.z = u4.z * r4.z + v4.z * q4.z;
            g.w = u4.w * r4.w + v4.w * q4.w;
            *(float4*)&Gs[j][(tid & 1) * 4] = g;
        }
        __syncthreads();
#pragma unroll
        for (int dd = 0; dd < DC; dd++) {
            float4 w0 = *(float4*)&W0_s[dd][kt * 4];
            float4 w1 = *(float4*)&W0_s[dd][256 + kt * 4];
#pragma unroll
            for (int jj = 0; jj < 9; jj++) {
                float g = Gs[jt + jj * 4][dd];   // warp-broadcast
                acc[jj][0] += g * w0.x;
                acc[jj][1] += g * w0.y;
                acc[jj][2] += g * w0.z;
                acc[jj][3] += g * w0.w;
                acc[jj][4] += g * w1.x;
                acc[jj][5] += g * w1.y;
                acc[jj][6] += g * w1.z;
                acc[jj][7] += g * w1.w;
            }
        }
        __syncthreads();
    }

    // per-thread score partials -> deterministic warp reduce
    const int kA = kt * 4;
    const int kB = 256 + kt * 4;
#pragma unroll
    for (int jj = 0; jj < 9; jj++) {
        float s = 0.f;
        s += wb_s[kA + 0] * tanhf(acc[jj][0] + b0_s[kA + 0]);
        s += wb_s[kA + 1] * tanhf(acc[jj][1] + b0_s[kA + 1]);
        s += wb_s[kA + 2] * tanhf(acc[jj][2] + b0_s[kA + 2]);
        s += wb_s[kA + 3] * tanhf(acc[jj][3] + b0_s[kA + 3]);
        s += wb_s[kB + 0] * tanhf(acc[jj][4] + b0_s[kB + 0]);
        s += wb_s[kB + 1] * tanhf(acc[jj][5] + b0_s[kB + 1]);
        s += wb_s[kB + 2] * tanhf(acc[jj][6] + b0_s[kB + 2]);
        s += wb_s[kB + 3] * tanhf(acc[jj][7] + b0_s[kB + 3]);
#pragma unroll
        for (int off = 16; off > 0; off >>= 1)
            s += __shfl_xor_sync(0xffffffffu, s, off);
        if ((tid & 31) == 0) warp_s[tid >> 5][jj] = s;   // all lanes of a warp share j
    }
    __syncthreads();
    if (tid < N_) {           // j = (j&3) + 4*(j>>2); warps 2*jt, 2*jt+1 hold partials
        int j4  = tid & 3;
        int jjj = tid >> 2;
        sc_s[tid] = warp_s[2 * j4][jjj] + warp_s[2 * j4 + 1][jjj];
    }
    __syncthreads();
    if (tid == 0) {           // softmax over 36 values, serial, deterministic
        float m = sc_s[0];
        for (int j = 1; j < N_; j++) m = fmaxf(m, sc_s[j]);
        float sum = 0.f;
        for (int j = 0; j < N_; j++) {
            float e = expf(sc_s[j] - m);
            att_s[j] = e;
            sum += e;
        }
        float inv = 1.f / sum;
        for (int j = 0; j < N_; j++) att_s[j] *= inv;
    }
    __syncthreads();

    // e_hat + residuals + output
    const float* objRow = obj + (size_t)bi * DF;
    const float* fusRow = fus + (size_t)bi * DF;
    float* outRow = out + (size_t)bi * DF;
    for (int d = tid * 4; d < DF; d += 1024) {
        float srx = 0.f, sry = 0.f, srz = 0.f, srw = 0.f;
        float sbx = 0.f, sby = 0.f, sbz = 0.f, sbw = 0.f;
#pragma unroll 6
        for (int j = 0; j < N_; j++) {
            float a = att_s[j];
            float4 r4 = *(const float4*)&rbB[(size_t)j * DF + d];
            float4 q4 = *(const float4*)&bbB[(size_t)j * DF + d];
            srx += a * r4.x; sry += a * r4.y; srz += a * r4.z; srw += a * r4.w;
            sbx += a * q4.x; sby += a * q4.y; sbz += a * q4.z; sbw += a * q4.w;
        }
        float4 u4 = *(float4*)&ra_s[d];
        float4 v4 = *(float4*)&ba_s[d];
        float4 o4 = *(const float4*)&objRow[d];
        float4 f4 = *(const float4*)&fusRow[d];
        float4 res;
        res.x = o4.x + f4.x + u4.x * srx + v4.x * sbx;
        res.y = o4.y + f4.y + u4.y * sry + v4.y * sby;
        res.z = o4.z + f4.z + u4.z * srz + v4.z * sbz;
        res.w = o4.w + f4.w + u4.w * srw + v4.w * sbw;
        *(float4*)&outRow[d] = res;
    }
}

extern "C" void kernel_launch(void* const* d_in, const int* in_sizes, int n_in,
                              void* d_out, int out_size) {
    const float* qe    = (const float*)d_in[0];   // [2304, 2048]
    const float* obj   = (const float*)d_in[1];   // [64, 36, 2048]
    const float* boxes = (const float*)d_in[2];   // [64, 36, 4]
    const float* Wq    = (const float*)d_in[3];
    const float* Wo    = (const float*)d_in[4];
    const float* Wfa   = (const float*)d_in[5];
    const float* Wfb   = (const float*)d_in[6];
    const float* Wba   = (const float*)d_in[7];
    const float* Wbb   = (const float*)d_in[8];
    const float* W0    = (const float*)d_in[9];
    const float* b0    = (const float*)d_in[10];
    const float* W1    = (const float*)d_in[11];
    // d_in[12] = b1 (cancels in softmax), d_in[13..] = scalars (hardcoded)
    float* out = (float*)d_out;

    float *tmp1, *tmp2, *ra, *rb, *ba, *bb;
    cudaGetSymbolAddress((void**)&tmp1, g_tmp1);
    cudaGetSymbolAddress((void**)&tmp2, g_tmp2);
    cudaGetSymbolAddress((void**)&ra,   g_ra);
    cudaGetSymbolAddress((void**)&rb,   g_rb);
    cudaGetSymbolAddress((void**)&ba,   g_ba);
    cudaGetSymbolAddress((void**)&bb,   g_bb);

    dim3 gg(DF / 128, ROWS / 128);   // (16, 18)
    int n4 = ROWS * DF / 4;

    sgemm128<<<gg, 256>>>(qe,   Wq,  tmp1, ROWS, DF, DF);
    sgemm128<<<gg, 256>>>(obj,  Wo,  tmp2, ROWS, DF, DF);
    elemmul <<<(n4 + 255) / 256, 256>>>(tmp1, tmp2, n4);     // tmp1 = fused
    sgemm128<<<gg, 256>>>(tmp1, Wfa, ra,   ROWS, DF, DF);
    sgemm128<<<gg, 256>>>(tmp1, Wfb, rb,   ROWS, DF, DF);
    boxproj <<<(n4 + 255) / 256, 256>>>(boxes, Wba, Wbb, ba, bb);
    relattn <<<ROWS, 256>>>(ra, rb, ba, bb, W0, b0, W1, obj, tmp1, out);
}

// round 3
// speedup vs baseline: 5.2162x; 3.1738x over previous
#include <cuda_runtime.h>
#include <math.h>
#include <stdint.h>

#define B_   64
#define N_   36
#define ROWS 2304      // B_*N_
#define DF   2048
#define DATT 512

// ---------------- scratch (static device buffers; runtime allocs banned) ----
__device__ float g_tmp1[ROWS * DF];   // qe@Wq, then unrounded fused
__device__ float g_tmp2[ROWS * DF];   // obj@Wo
__device__ float g_fusr[ROWS * DF];   // tf32-rounded fused (GEMM input)
__device__ float g_ra[ROWS * DF];
__device__ float g_rb[ROWS * DF];
__device__ float g_ba[ROWS * DF];
__device__ float g_bb[ROWS * DF];
__device__ float g_qer[ROWS * DF];    // tf32-rounded copies of GEMM inputs
__device__ float g_objr[ROWS * DF];
__device__ float g_Wqr[DF * DF];
__device__ float g_Wor[DF * DF];
__device__ float g_Wfar[DF * DF];
__device__ float g_Wfbr[DF * DF];
__device__ float g_W0r[DF * DATT];
__device__ float g_scp[4 * ROWS * N_]; // partial scores per 128-col slice
__device__ float g_attb[ROWS * N_];    // softmaxed attention

// ---------------- helpers ---------------------------------------------------
__device__ __forceinline__ float tf32r(float x) {
    uint32_t u; asm("cvt.rna.tf32.f32 %0, %1;" : "=r"(u) : "f"(x));
    return __uint_as_float(u);
}
__device__ __forceinline__ void mma8(float* d, const uint32_t* a, const uint32_t* b) {
    asm volatile("mma.sync.aligned.m16n8k8.row.col.f32.tf32.tf32.f32 "
                 "{%0,%1,%2,%3}, {%4,%5,%6,%7}, {%8,%9}, {%0,%1,%2,%3};"
                 : "+f"(d[0]), "+f"(d[1]), "+f"(d[2]), "+f"(d[3])
                 : "r"(a[0]), "r"(a[1]), "r"(a[2]), "r"(a[3]),
                   "r"(b[0]), "r"(b[1]));
}
__device__ __forceinline__ void cpa16(uint32_t s, const void* g) {
    asm volatile("cp.async.cg.shared.global [%0], [%1], 16;" :: "r"(s), "l"(g));
}
__device__ __forceinline__ void cpcommit() { asm volatile("cp.async.commit_group;"); }
__device__ __forceinline__ void cpwait0()  { asm volatile("cp.async.wait_group 0;"); }
__device__ __forceinline__ void cpwait1()  { asm volatile("cp.async.wait_group 1;"); }

// ---------------- elementwise kernels ---------------------------------------
__global__ void roundk(const float* __restrict__ s, float* __restrict__ d, int n4) {
    int i = blockIdx.x * blockDim.x + threadIdx.x;
    if (i < n4) {
        float4 v = ((const float4*)s)[i];
        v.x = tf32r(v.x); v.y = tf32r(v.y); v.z = tf32r(v.z); v.w = tf32r(v.w);
        ((float4*)d)[i] = v;
    }
}

// a = a*b (unrounded, for residual); c = tf32(a*b) (GEMM input)
__global__ void fusek(float* __restrict__ a, const float* __restrict__ b,
                      float* __restrict__ c, int n4) {
    int i = blockIdx.x * blockDim.x + threadIdx.x;
    if (i < n4) {
        float4 x = ((float4*)a)[i];
        float4 y = ((const float4*)b)[i];
        x.x *= y.x; x.y *= y.y; x.z *= y.z; x.w *= y.w;
        ((float4*)a)[i] = x;
        float4 r;
        r.x = tf32r(x.x); r.y = tf32r(x.y); r.z = tf32r(x.z); r.w = tf32r(x.w);
        ((float4*)c)[i] = r;
    }
}

// ba = boxes @ Wba, bb = boxes @ Wbb  (K = 4)
__global__ void boxproj(const float* __restrict__ boxes,
                        const float* __restrict__ Wba, const float* __restrict__ Wbb,
                        float* __restrict__ ba, float* __restrict__ bb) {
    int idx = blockIdx.x * blockDim.x + threadIdx.x;
    if (idx >= ROWS * (DF / 4)) return;
    int r  = idx / (DF / 4);
    int dq = (idx % (DF / 4)) * 4;
    float4 bx = *(const float4*)&boxes[r * 4];
    float c[4] = {bx.x, bx.y, bx.z, bx.w};
    float4 sa = make_float4(0.f, 0.f, 0.f, 0.f);
    float4 sb = make_float4(0.f, 0.f, 0.f, 0.f);
#pragma unroll
    for (int cc = 0; cc < 4; cc++) {
        float4 wa = *(const float4*)&Wba[cc * DF + dq];
        float4 wb = *(const float4*)&Wbb[cc * DF + dq];
        sa.x += c[cc] * wa.x; sa.y += c[cc] * wa.y; sa.z += c[cc] * wa.z; sa.w += c[cc] * wa.w;
        sb.x += c[cc] * wb.x; sb.y += c[cc] * wb.y; sb.z += c[cc] * wb.z; sb.w += c[cc] * wb.w;
    }
    *(float4*)&ba[(size_t)r * DF + dq] = sa;
    *(float4*)&bb[(size_t)r * DF + dq] = sb;
}

// ---------------------------------------------------------------------------
// tf32 tensor-core GEMM: C[M,N] = A @ B, fp32 storage (inputs pre-rounded).
// CTA tile 128x256, K-chunk 32, 8 warps of 64x64, cp.async double buffer.
// Smem A[m][36] (bank 4r+c, conflict-free), B[k][264] (bank 8c+r, cf).
// ---------------------------------------------------------------------------
__global__ __launch_bounds__(256)
void gemm_tc(const float* __restrict__ A, const float* __restrict__ Bg,
             float* __restrict__ C, int M, int N, int K) {
    extern __shared__ float sm[];
    float* As = sm;                // 2 x 128x36
    float* Bs = sm + 2 * 4608;     // 2 x 32x264
    const int tid  = threadIdx.x;
    const int lane = tid & 31, wid = tid >> 5;
    const int wm = (wid >> 2) * 64, wn = (wid & 3) * 64;
    const int m0 = blockIdx.y * 128, n0 = blockIdx.x * 256;
    uint32_t sA = (uint32_t)__cvta_generic_to_shared(As);
    uint32_t sB = (uint32_t)__cvta_generic_to_shared(Bs);

    float acc[4][8][4];
#pragma unroll
    for (int i = 0; i < 4; i++)
#pragma unroll
        for (int j = 0; j < 8; j++)
#pragma unroll
            for (int q = 0; q < 4; q++) acc[i][j][q] = 0.f;

    auto issue = [&](int kc, int s) {
        const float* Ag = A + (size_t)m0 * K + kc * 32;
#pragma unroll
        for (int q = 0; q < 4; q++) {
            int idx = tid + 256 * q;
            int m = idx >> 3, k4 = idx & 7;
            cpa16(sA + (uint32_t)(s * 4608 + m * 36 + k4 * 4) * 4,
                  Ag + (size_t)m * K + k4 * 4);
        }
        const float* Bgp = Bg + (size_t)(kc * 32) * N + n0;
#pragma unroll
        for (int q = 0; q < 8; q++) {
            int idx = tid + 256 * q;
            int kr = idx >> 6, n4 = idx & 63;
            cpa16(sB + (uint32_t)(s * 8448 + kr * 264 + n4 * 4) * 4,
                  Bgp + (size_t)kr * N + n4 * 4);
        }
        cpcommit();
    };

    const int NK = K / 32;
    issue(0, 0);
    for (int kc = 0; kc < NK; kc++) {
        int s = kc & 1;
        if (kc + 1 < NK) { issue(kc + 1, s ^ 1); cpwait1(); } else { cpwait0(); }
        __syncthreads();
        const float* Ab = As + s * 4608;
        const float* Bb = Bs + s * 8448;
#pragma unroll
        for (int kb = 0; kb < 32; kb += 8) {
            uint32_t af[4][4], bf[8][2];
#pragma unroll
            for (int mf = 0; mf < 4; mf++) {
                int ci = (wm + mf * 16 + (lane >> 2)) * 36 + kb + (lane & 3);
                af[mf][0] = __float_as_uint(Ab[ci]);
                af[mf][1] = __float_as_uint(Ab[ci + 8 * 36]);
                af[mf][2] = __float_as_uint(Ab[ci + 4]);
                af[mf][3] = __float_as_uint(Ab[ci + 8 * 36 + 4]);
            }
#pragma unroll
            for (int nf = 0; nf < 8; nf++) {
                int ci = (kb + (lane & 3)) * 264 + wn + nf * 8 + (lane >> 2);
                bf[nf][0] = __float_as_uint(Bb[ci]);
                bf[nf][1] = __float_as_uint(Bb[ci + 4 * 264]);
            }
#pragma unroll
            for (int mf = 0; mf < 4; mf++)
#pragma unroll
                for (int nf = 0; nf < 8; nf++)
                    mma8(acc[mf][nf], af[mf], bf[nf]);
        }
        __syncthreads();
    }

#pragma unroll
    for (int mf = 0; mf < 4; mf++) {
        int r0 = m0 + wm + mf * 16 + (lane >> 2);
#pragma unroll
        for (int nf = 0; nf < 8; nf++) {
            int c = n0 + wn + nf * 8 + 2 * (lane & 3);
            *(float2*)&C[(size_t)r0 * N + c] = make_float2(acc[mf][nf][0], acc[mf][nf][1]);
            *(float2*)&C[(size_t)(r0 + 8) * N + c] = make_float2(acc[mf][nf][2], acc[mf][nf][3]);
        }
    }
}

// ---------------------------------------------------------------------------
// Relation-attention score GEMM on tensor cores.
// Grid (slice=4 x 128 att-cols, ig=9 x 4 i's, b=64). M=144 (4i x 36j exact).
// G[r][d]=tf32(ra_i[d]*rb_j[d]+ba_i[d]*bb_j[d]) built per 32-d chunk in smem.
// 6 warps (3M x 2N), warp tile 48x64. Epilogue: partial score via W1*tanh.
// ---------------------------------------------------------------------------
__global__ __launch_bounds__(192, 2)
void relattn_tc(const float* __restrict__ ra, const float* __restrict__ rb,
                const float* __restrict__ ba, const float* __restrict__ bb,
                const float* __restrict__ W0r, const float* __restrict__ b0,
                const float* __restrict__ W1, float* __restrict__ scp) {
    extern __shared__ float sm[];
    float* Gs  = sm;               // 2 x 144x36
    float* Ws  = sm + 10368;       // 2 x 32x136
    float* red = sm + 19072;       // 144 x 2
    const int tid = threadIdx.x, lane = tid & 31, wid = tid >> 5;
    const int wm = (wid >> 1) * 48, wn = (wid & 1) * 64;
    const int slice = blockIdx.x, ig = blockIdx.y, b = blockIdx.z;
    const float* rbB = rb + (size_t)b * N_ * DF;
    const float* bbB = bb + (size_t)b * N_ * DF;
    const float* raB = ra + ((size_t)b * N_ + ig * 4) * DF;
    const float* baB = ba + ((size_t)b * N_ + ig * 4) * DF;
    const float* W0p = W0r + slice * 128;
    uint32_t sW = (uint32_t)__cvta_generic_to_shared(Ws);

    float acc[3][8][4];
#pragma unroll
    for (int i = 0; i < 3; i++)
#pragma unroll
        for (int j = 0; j < 8; j++)
#pragma unroll
            for (int q = 0; q < 4; q++) acc[i][j][q] = 0.f;

    auto issueW = [&](int kc, int s) {
#pragma unroll
        for (int q = 0; q < 6; q++) {
            int idx = tid + 192 * q;
            if (idx < 1024) {
                int kr = idx >> 5, n4 = idx & 31;
                cpa16(sW + (uint32_t)(s * 4352 + kr * 136 + n4 * 4) * 4,
                      W0p + (size_t)(kc * 32 + kr) * DATT + n4 * 4);
            }
        }
        cpcommit();
    };
    auto buildG = [&](int kc, int s) {
        float* Gb = Gs + s * 5184;
        int d0 = kc * 32;
#pragma unroll
        for (int q = 0; q < 6; q++) {
            int idx = tid + 192 * q;
            int r = idx >> 3, dq = (idx & 7) * 4;
            int il = r / 36, j = r - il * 36;
            float4 r4 = *(const float4*)&rbB[(size_t)j * DF + d0 + dq];
            float4 q4 = *(const float4*)&bbB[(size_t)j * DF + d0 + dq];
            float4 u4 = *(const float4*)&raB[(size_t)il * DF + d0 + dq];
            float4 v4 = *(const float4*)&baB[(size_t)il * DF + d0 + dq];
            float4 g;
            g.x = tf32r(u4.x * r4.x + v4.x * q4.x);
            g.y = tf32r(u4.y * r4.y + v4.y * q4.y);
            g.z = tf32r(u4.z * r4.z + v4.z * q4.z);
            g.w = tf32r(u4.w * r4.w + v4.w * q4.w);
            *(float4*)&Gb[r * 36 + dq] = g;
        }
    };

    issueW(0, 0);
    buildG(0, 0);
    cpwait0();
    __syncthreads();
    for (int kc = 0; kc < 64; kc++) {
        int s = kc & 1;
        if (kc < 63) issueW(kc + 1, s ^ 1);
        const float* Gb = Gs + s * 5184;
        const float* Wb = Ws + s * 4352;
#pragma unroll
        for (int kb = 0; kb < 32; kb += 8) {
            uint32_t af[3][4], bf[8][2];
#pragma unroll
            for (int mf = 0; mf < 3; mf++) {
                int ci = (wm + mf * 16 + (lane >> 2)) * 36 + kb + (lane & 3);
                af[mf][0] = __float_as_uint(Gb[ci]);
                af[mf][1] = __float_as_uint(Gb[ci + 8 * 36]);
                af[mf][2] = __float_as_uint(Gb[ci + 4]);
                af[mf][3] = __float_as_uint(Gb[ci + 8 * 36 + 4]);
            }
#pragma unroll
            for (int nf = 0; nf < 8; nf++) {
                int ci = (kb + (lane & 3)) * 136 + wn + nf * 8 + (lane >> 2);
                bf[nf][0] = __float_as_uint(Wb[ci]);
                bf[nf][1] = __float_as_uint(Wb[ci + 4 * 136]);
            }
#pragma unroll
            for (int mf = 0; mf < 3; mf++)
#pragma unroll
                for (int nf = 0; nf < 8; nf++)
                    mma8(acc[mf][nf], af[mf], bf[nf]);
        }
        if (kc < 63) buildG(kc + 1, s ^ 1);
        cpwait0();
        __syncthreads();
    }

    // epilogue: partial scores over this 128-col slice (deterministic order)
    const float* b0g = b0 + slice * 128;
    const float* W1g = W1 + slice * 128;
#pragma unroll
    for (int mf = 0; mf < 3; mf++) {
        float s0 = 0.f, s1 = 0.f;
#pragma unroll
        for (int nf = 0; nf < 8; nf++) {
            int c0 = wn + nf * 8 + 2 * (lane & 3);
            float w0 = W1g[c0],     e0 = b0g[c0];
            float w1 = W1g[c0 + 1], e1 = b0g[c0 + 1];
            s0 += w0 * tanhf(acc[mf][nf][0] + e0) + w1 * tanhf(acc[mf][nf][1] + e1);
            s1 += w0 * tanhf(acc[mf][nf][2] + e0) + w1 * tanhf(acc[mf][nf][3] + e1);
        }
        s0 += __shfl_xor_sync(0xffffffffu, s0, 1);
        s0 += __shfl_xor_sync(0xffffffffu, s0, 2);
        s1 += __shfl_xor_sync(0xffffffffu, s1, 1);
        s1 += __shfl_xor_sync(0xffffffffu, s1, 2);
        if ((lane & 3) == 0) {
            int r = wm + mf * 16 + (lane >> 2);
            red[r * 2 + (wid & 1)]       = s0;
            red[(r + 8) * 2 + (wid & 1)] = s1;
        }
    }
    __syncthreads();
    if (tid < 144) {
        float tot = red[tid * 2] + red[tid * 2 + 1];
        scp[(((size_t)slice * B_ + b) * 9 + ig) * 144 + tid] = tot;
    }
}

// softmax over j for each (b,i); one thread per row, serial = deterministic
__global__ void attk(const float* __restrict__ scp, float* __restrict__ att) {
    int bi = blockIdx.x * blockDim.x + threadIdx.x;
    if (bi >= ROWS) return;
    int b = bi / N_, i = bi - b * N_;
    int ig = i >> 2, il = i & 3;
    float sc[N_];
#pragma unroll 4
    for (int j = 0; j < N_; j++) {
        float s = 0.f;
#pragma unroll
        for (int sl = 0; sl < 4; sl++)
            s += scp[(((size_t)sl * B_ + b) * 9 + ig) * 144 + il * 36 + j];
        sc[j] = s;
    }
    float m = sc[0];
    for (int j = 1; j < N_; j++) m = fmaxf(m, sc[j]);
    float sum = 0.f;
    for (int j = 0; j < N_; j++) { sc[j] = expf(sc[j] - m); sum += sc[j]; }
    float inv = 1.f / sum;
    for (int j = 0; j < N_; j++) att[(size_t)bi * N_ + j] = sc[j] * inv;
}

// out = obj + fused + ra.*(att@rb) + ba.*(att@bb); grid (16 d-slices, B)
__global__ __launch_bounds__(256)
void ehat_fin(const float* __restrict__ att,
              const float* __restrict__ ra, const float* __restrict__ rb,
              const float* __restrict__ ba, const float* __restrict__ bb,
              const float* __restrict__ obj, const float* __restrict__ fus,
              float* __restrict__ out) {
    __shared__ float att_s[N_][N_ + 1];
    const int tid = threadIdx.x;
    const int b = blockIdx.y, d0 = blockIdx.x * 128;
    const int d = tid & 127, half = tid >> 7;
    for (int idx = tid; idx < N_ * N_; idx += 256)
        att_s[idx / N_][idx % N_] = att[(size_t)(b * N_ + idx / N_) * N_ + idx % N_];
    __syncthreads();
    const float* rbB = rb + (size_t)b * N_ * DF + d0 + d;
    const float* bbB = bb + (size_t)b * N_ * DF + d0 + d;
    float accR[18], accB[18];
#pragma unroll
    for (int i = 0; i < 18; i++) { accR[i] = 0.f; accB[i] = 0.f; }
    for (int j = 0; j < N_; j++) {
        float rv = rbB[(size_t)j * DF];
        float bv = bbB[(size_t)j * DF];
#pragma unroll
        for (int i = 0; i < 18; i++) {
            float a = att_s[half * 18 + i][j];
            accR[i] += a * rv;
            accB[i] += a * bv;
        }
    }
#pragma unroll
    for (int i = 0; i < 18; i++) {
        size_t row = (size_t)b * N_ + half * 18 + i;
        size_t off = row * DF + d0 + d;
        out[off] = obj[off] + fus[off] + ra[off] * accR[i] + ba[off] * accB[i];
    }
}

extern "C" void kernel_launch(void* const* d_in, const int* in_sizes, int n_in,
                              void* d_out, int out_size) {
    const float* qe    = (const float*)d_in[0];
    const float* obj   = (const float*)d_in[1];
    const float* boxes = (const float*)d_in[2];
    const float* Wq    = (const float*)d_in[3];
    const float* Wo    = (const float*)d_in[4];
    const float* Wfa   = (const float*)d_in[5];
    const float* Wfb   = (const float*)d_in[6];
    const float* Wba   = (const float*)d_in[7];
    const float* Wbb   = (const float*)d_in[8];
    const float* W0    = (const float*)d_in[9];
    const float* b0    = (const float*)d_in[10];
    const float* W1    = (const float*)d_in[11];
    float* out = (float*)d_out;

    float *tmp1, *tmp2, *fusr, *ra, *rb, *ba, *bb;
    float *qer, *objr, *Wqr, *Wor, *Wfar, *Wfbr, *W0r, *scp, *attb;
    cudaGetSymbolAddress((void**)&tmp1, g_tmp1);
    cudaGetSymbolAddress((void**)&tmp2, g_tmp2);
    cudaGetSymbolAddress((void**)&fusr, g_fusr);
    cudaGetSymbolAddress((void**)&ra,   g_ra);
    cudaGetSymbolAddress((void**)&rb,   g_rb);
    cudaGetSymbolAddress((void**)&ba,   g_ba);
    cudaGetSymbolAddress((void**)&bb,   g_bb);
    cudaGetSymbolAddress((void**)&qer,  g_qer);
    cudaGetSymbolAddress((void**)&objr, g_objr);
    cudaGetSymbolAddress((void**)&Wqr,  g_Wqr);
    cudaGetSymbolAddress((void**)&Wor,  g_Wor);
    cudaGetSymbolAddress((void**)&Wfar, g_Wfar);
    cudaGetSymbolAddress((void**)&Wfbr, g_Wfbr);
    cudaGetSymbolAddress((void**)&W0r,  g_W0r);
    cudaGetSymbolAddress((void**)&scp,  g_scp);
    cudaGetSymbolAddress((void**)&attb, g_attb);

    cudaFuncSetAttribute(gemm_tc, cudaFuncAttributeMaxDynamicSharedMemorySize, 104448);
    cudaFuncSetAttribute(relattn_tc, cudaFuncAttributeMaxDynamicSharedMemorySize, 77440);

    const int nIO = ROWS * DF / 4;     // 1179648
    const int nW  = DF * DF / 4;       // 1048576
    const int nW0 = DF * DATT / 4;     // 262144

    roundk<<<(nIO + 255) / 256, 256>>>(qe,  qer,  nIO);
    roundk<<<(nIO + 255) / 256, 256>>>(obj, objr, nIO);
    roundk<<<(nW  + 255) / 256, 256>>>(Wq,  Wqr,  nW);
    roundk<<<(nW  + 255) / 256, 256>>>(Wo,  Wor,  nW);
    roundk<<<(nW  + 255) / 256, 256>>>(Wfa, Wfar, nW);
    roundk<<<(nW  + 255) / 256, 256>>>(Wfb, Wfbr, nW);
    roundk<<<(nW0 + 255) / 256, 256>>>(W0,  W0r,  nW0);

    dim3 gg(DF / 256, ROWS / 128);     // (8, 18)
    gemm_tc<<<gg, 256, 104448>>>(qer,  Wqr, tmp1, ROWS, DF, DF);
    gemm_tc<<<gg, 256, 104448>>>(objr, Wor, tmp2, ROWS, DF, DF);
    fusek<<<(nIO + 255) / 256, 256>>>(tmp1, tmp2, fusr, nIO);   // tmp1=fused, fusr=tf32(fused)
    gemm_tc<<<gg, 256, 104448>>>(fusr, Wfar, ra, ROWS, DF, DF);
    gemm_tc<<<gg, 256, 104448>>>(fusr, Wfbr, rb, ROWS, DF, DF);
    boxproj<<<(nIO + 255) / 256, 256>>>(boxes, Wba, Wbb, ba, bb);

    relattn_tc<<<dim3(4, 9, B_), 192, 77440>>>(ra, rb, ba, bb, W0r, b0, W1, scp);
    attk<<<(ROWS + 127) / 128, 128>>>(scp, attb);
    ehat_fin<<<dim3(16, B_), 256>>>(attb, ra, rb, ba, bb, obj, tmp1, out);
}

// round 5
// speedup vs baseline: 5.4624x; 1.0472x over previous
#include <cuda_runtime.h>
#include <math.h>
#include <stdint.h>

#define B_   64
#define N_   36
#define ROWS 2304      // B_*N_
#define DF   2048
#define DATT 512

// ---------------- scratch (static device buffers; runtime allocs banned) ----
__device__ float g_tmp1[ROWS * DF];   // qe@Wq, then unrounded fused
__device__ float g_tmp2[ROWS * DF];   // obj@Wo
__device__ float g_fusr[ROWS * DF];   // rna-rounded fused (GEMM input)
__device__ float g_ra[ROWS * DF];
__device__ float g_rb[ROWS * DF];
__device__ float g_ba[ROWS * DF];
__device__ float g_bb[ROWS * DF];
__device__ float g_qer[ROWS * DF];    // rna-rounded GEMM inputs
__device__ float g_objr[ROWS * DF];
__device__ float g_Wqr[DF * DF];
__device__ float g_Wor[DF * DF];
__device__ float g_Wfar[DF * DF];
__device__ float g_Wfbr[DF * DF];
__device__ float g_W0r[DF * DATT];
__device__ float g_scp[2 * 9 * B_ * 144]; // partial scores per 256-col slice
__device__ float g_attb[ROWS * N_];       // softmaxed attention

// ---------------- helpers ---------------------------------------------------
__device__ __forceinline__ float tf32r(float x) {
    uint32_t u; asm("cvt.rna.tf32.f32 %0, %1;" : "=r"(u) : "f"(x));
    return __uint_as_float(u);
}
__device__ __forceinline__ void mma8(float* d, const uint32_t* a, const uint32_t* b) {
    asm volatile("mma.sync.aligned.m16n8k8.row.col.f32.tf32.tf32.f32 "
                 "{%0,%1,%2,%3}, {%4,%5,%6,%7}, {%8,%9}, {%0,%1,%2,%3};"
                 : "+f"(d[0]), "+f"(d[1]), "+f"(d[2]), "+f"(d[3])
                 : "r"(a[0]), "r"(a[1]), "r"(a[2]), "r"(a[3]),
                   "r"(b[0]), "r"(b[1]));
}
__device__ __forceinline__ void cpa16(uint32_t s, const void* g) {
    asm volatile("cp.async.cg.shared.global [%0], [%1], 16;" :: "r"(s), "l"(g));
}
__device__ __forceinline__ void cpcommit() { asm volatile("cp.async.commit_group;"); }
__device__ __forceinline__ void cpwait0()  { asm volatile("cp.async.wait_group 0;"); }
__device__ __forceinline__ void cpwait1()  { asm volatile("cp.async.wait_group 1;"); }

// ---------------- elementwise kernels ---------------------------------------
__global__ void roundk(const float* __restrict__ s, float* __restrict__ d, int n4) {
    int i = blockIdx.x * blockDim.x + threadIdx.x;
    if (i < n4) {
        float4 v = ((const float4*)s)[i];
        v.x = tf32r(v.x); v.y = tf32r(v.y); v.z = tf32r(v.z); v.w = tf32r(v.w);
        ((float4*)d)[i] = v;
    }
}

// a = a*b (unrounded, for residual); c = tf32_rna(a*b) (GEMM input)
__global__ void fusek(float* __restrict__ a, const float* __restrict__ b,
                      float* __restrict__ c, int n4) {
    int i = blockIdx.x * blockDim.x + threadIdx.x;
    if (i < n4) {
        float4 x = ((float4*)a)[i];
        float4 y = ((const float4*)b)[i];
        x.x *= y.x; x.y *= y.y; x.z *= y.z; x.w *= y.w;
        ((float4*)a)[i] = x;
        float4 r;
        r.x = tf32r(x.x); r.y = tf32r(x.y); r.z = tf32r(x.z); r.w = tf32r(x.w);
        ((float4*)c)[i] = r;
    }
}

// ba = boxes @ Wba, bb = boxes @ Wbb  (K = 4)
__global__ void boxproj(const float* __restrict__ boxes,
                        const float* __restrict__ Wba, const float* __restrict__ Wbb,
                        float* __restrict__ ba, float* __restrict__ bb) {
    int idx = blockIdx.x * blockDim.x + threadIdx.x;
    if (idx >= ROWS * (DF / 4)) return;
    int r  = idx / (DF / 4);
    int dq = (idx % (DF / 4)) * 4;
    float4 bx = *(const float4*)&boxes[r * 4];
    float c[4] = {bx.x, bx.y, bx.z, bx.w};
    float4 sa = make_float4(0.f, 0.f, 0.f, 0.f);
    float4 sb = make_float4(0.f, 0.f, 0.f, 0.f);
#pragma unroll
    for (int cc = 0; cc < 4; cc++) {
        float4 wa = *(const float4*)&Wba[cc * DF + dq];
        float4 wb = *(const float4*)&Wbb[cc * DF + dq];
        sa.x += c[cc] * wa.x; sa.y += c[cc] * wa.y; sa.z += c[cc] * wa.z; sa.w += c[cc] * wa.w;
        sb.x += c[cc] * wb.x; sb.y += c[cc] * wb.y; sb.z += c[cc] * wb.z; sb.w += c[cc] * wb.w;
    }
    *(float4*)&ba[(size_t)r * DF + dq] = sa;
    *(float4*)&bb[(size_t)r * DF + dq] = sb;
}

// ---------------------------------------------------------------------------
// tf32 tensor-core GEMM: C[M,N] = A @ B (inputs pre-rounded rna).
// CTA 128x256, K-chunk 32, 8 warps of 64x64, cp.async double buffer.
// Logical-k permutation (slot c <-> phys 2c, slot c+4 <-> 2c+1): A fragments
// load as LDS.64 pairs. Pitches: A 40, B 260 (both conflict-free per phase).
// ---------------------------------------------------------------------------
__global__ __launch_bounds__(256)
void gemm_tc(const float* __restrict__ A, const float* __restrict__ Bg,
             float* __restrict__ C, int M, int N, int K) {
    extern __shared__ float sm[];
    float* As = sm;                // 2 x 128x40
    float* Bs = sm + 2 * 5120;     // 2 x 32x260
    const int tid  = threadIdx.x;
    const int lane = tid & 31, wid = tid >> 5;
    const int cc = lane & 3, q = lane >> 2;
    const int wm = (wid >> 2) * 64, wn = (wid & 3) * 64;
    const int m0 = blockIdx.y * 128, n0 = blockIdx.x * 256;
    uint32_t sA = (uint32_t)__cvta_generic_to_shared(As);
    uint32_t sB = (uint32_t)__cvta_generic_to_shared(Bs);

    float acc[4][8][4];
#pragma unroll
    for (int i = 0; i < 4; i++)
#pragma unroll
        for (int j = 0; j < 8; j++)
#pragma unroll
            for (int p = 0; p < 4; p++) acc[i][j][p] = 0.f;

    auto issue = [&](int kc, int s) {
        const float* Ag = A + (size_t)m0 * K + kc * 32;
#pragma unroll
        for (int p = 0; p < 4; p++) {
            int idx = tid + 256 * p;
            int m = idx >> 3, k4 = idx & 7;
            cpa16(sA + (uint32_t)(s * 5120 + m * 40 + k4 * 4) * 4,
                  Ag + (size_t)m * K + k4 * 4);
        }
        const float* Bgp = Bg + (size_t)(kc * 32) * N + n0;
#pragma unroll
        for (int p = 0; p < 8; p++) {
            int idx = tid + 256 * p;
            int kr = idx >> 6, n4 = idx & 63;
            cpa16(sB + (uint32_t)(s * 8320 + kr * 260 + n4 * 4) * 4,
                  Bgp + (size_t)kr * N + n4 * 4);
        }
        cpcommit();
    };

    const int NK = K / 32;
    issue(0, 0);
    for (int kc = 0; kc < NK; kc++) {
        int s = kc & 1;
        if (kc + 1 < NK) { issue(kc + 1, s ^ 1); cpwait1(); } else { cpwait0(); }
        __syncthreads();
        const float* Ab = As + s * 5120;
        const float* Bb = Bs + s * 8320;
#pragma unroll
        for (int kb = 0; kb < 32; kb += 8) {
            uint32_t af[4][4], bf[8][2];
#pragma unroll
            for (int mf = 0; mf < 4; mf++) {
                int r = wm + mf * 16 + q;
                float2 lo = *(const float2*)&Ab[r * 40 + kb + 2 * cc];
                float2 hi = *(const float2*)&Ab[(r + 8) * 40 + kb + 2 * cc];
                af[mf][0] = __float_as_uint(lo.x);
                af[mf][1] = __float_as_uint(hi.x);
                af[mf][2] = __float_as_uint(lo.y);
                af[mf][3] = __float_as_uint(hi.y);
            }
#pragma unroll
            for (int nf = 0; nf < 8; nf++) {
                int ci = (kb + 2 * cc) * 260 + wn + nf * 8 + q;
                bf[nf][0] = __float_as_uint(Bb[ci]);
                bf[nf][1] = __float_as_uint(Bb[ci + 260]);
            }
#pragma unroll
            for (int mf = 0; mf < 4; mf++)
#pragma unroll
                for (int nf = 0; nf < 8; nf++)
                    mma8(acc[mf][nf], af[mf], bf[nf]);
        }
        __syncthreads();
    }

#pragma unroll
    for (int mf = 0; mf < 4; mf++) {
        int r0 = m0 + wm + mf * 16 + q;
#pragma unroll
        for (int nf = 0; nf < 8; nf++) {
            int c = n0 + wn + nf * 8 + 2 * cc;
            *(float2*)&C[(size_t)r0 * N + c] = make_float2(acc[mf][nf][0], acc[mf][nf][1]);
            *(float2*)&C[(size_t)(r0 + 8) * N + c] = make_float2(acc[mf][nf][2], acc[mf][nf][3]);
        }
    }
}

// ---------------------------------------------------------------------------
// Relation-attention score GEMM, v2 (staged operands + rna-rounded G).
// Grid (slice=2 x 256 att-cols, ig=9 x 4 i's, b=64). M=144 (4i x 36j exact).
// ---------------------------------------------------------------------------
__global__ __launch_bounds__(384)
void relattn_tc(const float* __restrict__ ra, const float* __restrict__ rb,
                const float* __restrict__ ba, const float* __restrict__ bb,
                const float* __restrict__ W0r, const float* __restrict__ b0,
                const float* __restrict__ W1, float* __restrict__ scp) {
    extern __shared__ float sm[];
    float* Gs  = sm;                 // 2 x 144x40 = 2 x 5760
    float* Ws  = sm + 11520;         // 2 x 32x260 = 2 x 8320
    float* rbS = sm + 28160;         // 2 x 36x36
    float* bbS = sm + 30752;         // 2 x 36x36
    float* raS = sm + 33344;         // 2 x 4x36
    float* baS = sm + 33632;         // 2 x 4x36
    float* red = sm + 33920;         // 144 x 4
    const int tid = threadIdx.x, lane = tid & 31, wid = tid >> 5;
    const int cc = lane & 3, q = lane >> 2;
    const int wm = (wid >> 2) * 48, wn = (wid & 3) * 64;
    const int slice = blockIdx.x, ig = blockIdx.y, b = blockIdx.z;
    const float* rbB = rb + (size_t)b * N_ * DF;
    const float* bbB = bb + (size_t)b * N_ * DF;
    const float* raB = ra + ((size_t)b * N_ + ig * 4) * DF;
    const float* baB = ba + ((size_t)b * N_ + ig * 4) * DF;
    const float* W0p = W0r + slice * 256;
    uint32_t uW  = (uint32_t)__cvta_generic_to_shared(Ws);
    uint32_t uRB = (uint32_t)__cvta_generic_to_shared(rbS);
    uint32_t uBB = (uint32_t)__cvta_generic_to_shared(bbS);
    uint32_t uRA = (uint32_t)__cvta_generic_to_shared(raS);
    uint32_t uBA = (uint32_t)__cvta_generic_to_shared(baS);

    float acc[3][8][4];
#pragma unroll
    for (int i = 0; i < 3; i++)
#pragma unroll
        for (int j = 0; j < 8; j++)
#pragma unroll
            for (int p = 0; p < 4; p++) acc[i][j][p] = 0.f;

    auto issueStage = [&](int kc, int s) {
#pragma unroll
        for (int p = 0; p < 6; p++) {
            int idx = tid + 384 * p;
            if (idx < 2048) {
                int kr = idx >> 6, n4 = idx & 63;
                cpa16(uW + (uint32_t)(s * 8320 + kr * 260 + n4 * 4) * 4,
                      W0p + (size_t)(kc * 32 + kr) * DATT + n4 * 4);
            }
        }
#pragma unroll
        for (int p = 0; p < 2; p++) {
            int idx = tid + 384 * p;
            if (idx < 640) {
                int c4 = (idx & 7) * 4;
                int gc = kc * 32 + c4;
                if (idx < 288) {
                    int j = idx >> 3;
                    cpa16(uRB + (uint32_t)(s * 1296 + j * 36 + c4) * 4,
                          rbB + (size_t)j * DF + gc);
                } else if (idx < 576) {
                    int j = (idx - 288) >> 3;
                    cpa16(uBB + (uint32_t)(s * 1296 + j * 36 + c4) * 4,
                          bbB + (size_t)j * DF + gc);
                } else if (idx < 608) {
                    int r = (idx - 576) >> 3;
                    cpa16(uRA + (uint32_t)(s * 144 + r * 36 + c4) * 4,
                          raB + (size_t)r * DF + gc);
                } else {
                    int r = (idx - 608) >> 3;
                    cpa16(uBA + (uint32_t)(s * 144 + r * 36 + c4) * 4,
                          baB + (size_t)r * DF + gc);
                }
            }
        }
        cpcommit();
    };

    issueStage(0, 0);
    for (int kc = 0; kc < 64; kc++) {
        int s = kc & 1;
        cpwait0();
        __syncthreads();
        if (kc < 63) issueStage(kc + 1, s ^ 1);
        {   // build rna-rounded G chunk [144][32] from staged raw operands
            float* Gb = Gs + s * 5760;
            const float* rs = rbS + s * 1296;
            const float* bs = bbS + s * 1296;
            const float* us = raS + s * 144;
            const float* vs = baS + s * 144;
#pragma unroll
            for (int p = 0; p < 3; p++) {
                int idx = tid + 384 * p;   // < 1152
                int r = idx >> 3, dq = (idx & 7) * 4;
                int il = r / 36, j = r - il * 36;
                float4 rv = *(const float4*)&rs[j * 36 + dq];
                float4 bv = *(const float4*)&bs[j * 36 + dq];
                float4 u  = *(const float4*)&us[il * 36 + dq];
                float4 v  = *(const float4*)&vs[il * 36 + dq];
                float4 g;
                g.x = tf32r(u.x * rv.x + v.x * bv.x);
                g.y = tf32r(u.y * rv.y + v.y * bv.y);
                g.z = tf32r(u.z * rv.z + v.z * bv.z);
                g.w = tf32r(u.w * rv.w + v.w * bv.w);
                *(float4*)&Gb[r * 40 + dq] = g;
            }
        }
        __syncthreads();
        const float* Gb = Gs + s * 5760;
        const float* Wb = Ws + s * 8320;
#pragma unroll
        for (int kb = 0; kb < 32; kb += 8) {
            uint32_t af[3][4], bf[8][2];
#pragma unroll
            for (int mf = 0; mf < 3; mf++) {
                int r = wm + mf * 16 + q;
                float2 lo = *(const float2*)&Gb[r * 40 + kb + 2 * cc];
                float2 hi = *(const float2*)&Gb[(r + 8) * 40 + kb + 2 * cc];
                af[mf][0] = __float_as_uint(lo.x);
                af[mf][1] = __float_as_uint(hi.x);
                af[mf][2] = __float_as_uint(lo.y);
                af[mf][3] = __float_as_uint(hi.y);
            }
#pragma unroll
            for (int nf = 0; nf < 8; nf++) {
                int ci = (kb + 2 * cc) * 260 + wn + nf * 8 + q;
                bf[nf][0] = __float_as_uint(Wb[ci]);
                bf[nf][1] = __float_as_uint(Wb[ci + 260]);
            }
#pragma unroll
            for (int mf = 0; mf < 3; mf++)
#pragma unroll
                for (int nf = 0; nf < 8; nf++)
                    mma8(acc[mf][nf], af[mf], bf[nf]);
        }
    }
    __syncthreads();

    // epilogue: partial scores over this 256-col slice (deterministic order)
    const float* b0g = b0 + slice * 256;
    const float* W1g = W1 + slice * 256;
#pragma unroll
    for (int mf = 0; mf < 3; mf++) {
        float s0 = 0.f, s1 = 0.f;
#pragma unroll
        for (int nf = 0; nf < 8; nf++) {
            int c0 = wn + nf * 8 + 2 * cc;
            float w0 = W1g[c0],     e0 = b0g[c0];
            float w1 = W1g[c0 + 1], e1 = b0g[c0 + 1];
            s0 += w0 * tanhf(acc[mf][nf][0] + e0) + w1 * tanhf(acc[mf][nf][1] + e1);
            s1 += w0 * tanhf(acc[mf][nf][2] + e0) + w1 * tanhf(acc[mf][nf][3] + e1);
        }
        s0 += __shfl_xor_sync(0xffffffffu, s0, 1);
        s0 += __shfl_xor_sync(0xffffffffu, s0, 2);
        s1 += __shfl_xor_sync(0xffffffffu, s1, 1);
        s1 += __shfl_xor_sync(0xffffffffu, s1, 2);
        if (cc == 0) {
            int r = wm + mf * 16 + q;
            red[r * 4 + (wid & 3)]       = s0;
            red[(r + 8) * 4 + (wid & 3)] = s1;
        }
    }
    __syncthreads();
    if (tid < 144) {
        float tot = red[tid * 4] + red[tid * 4 + 1] + red[tid * 4 + 2] + red[tid * 4 + 3];
        scp[(((size_t)slice * B_ + b) * 9 + ig) * 144 + tid] = tot;
    }
}

// softmax over j for each (b,i); one thread per row, serial = deterministic
__global__ void attk(const float* __restrict__ scp, float* __restrict__ att) {
    int bi = blockIdx.x * blockDim.x + threadIdx.x;
    if (bi >= ROWS) return;
    int b = bi / N_, i = bi - b * N_;
    int ig = i >> 2, il = i & 3;
    float sc[N_];
#pragma unroll 4
    for (int j = 0; j < N_; j++) {
        sc[j] = scp[(((size_t)b) * 9 + ig) * 144 + il * 36 + j]
              + scp[(((size_t)B_ + b) * 9 + ig) * 144 + il * 36 + j];
    }
    float m = sc[0];
    for (int j = 1; j < N_; j++) m = fmaxf(m, sc[j]);
    float sum = 0.f;
    for (int j = 0; j < N_; j++) { sc[j] = expf(sc[j] - m); sum += sc[j]; }
    float inv = 1.f / sum;
    for (int j = 0; j < N_; j++) att[(size_t)bi * N_ + j] = sc[j] * inv;
}

// out = obj + fused + ra.*(att@rb) + ba.*(att@bb); grid (16 d-slices, B)
__global__ __launch_bounds__(256)
void ehat_fin(const float* __restrict__ att,
              const float* __restrict__ ra, const float* __restrict__ rb,
              const float* __restrict__ ba, const float* __restrict__ bb,
              const float* __restrict__ obj, const float* __restrict__ fus,
              float* __restrict__ out) {
    __shared__ float att_s[N_][N_ + 1];
    const int tid = threadIdx.x;
    const int b = blockIdx.y, d0 = blockIdx.x * 128;
    const int d = tid & 127, half = tid >> 7;
    for (int idx = tid; idx < N_ * N_; idx += 256)
        att_s[idx / N_][idx % N_] = att[(size_t)(b * N_ + idx / N_) * N_ + idx % N_];
    __syncthreads();
    const float* rbB = rb + (size_t)b * N_ * DF + d0 + d;
    const float* bbB = bb + (size_t)b * N_ * DF + d0 + d;
    float accR[18], accB[18];
#pragma unroll
    for (int i = 0; i < 18; i++) { accR[i] = 0.f; accB[i] = 0.f; }
    for (int j = 0; j < N_; j++) {
        float rv = rbB[(size_t)j * DF];
        float bv = bbB[(size_t)j * DF];
#pragma unroll
        for (int i = 0; i < 18; i++) {
            float a = att_s[half * 18 + i][j];
            accR[i] += a * rv;
            accB[i] += a * bv;
        }
    }
#pragma unroll
    for (int i = 0; i < 18; i++) {
        size_t row = (size_t)b * N_ + half * 18 + i;
        size_t off = row * DF + d0 + d;
        out[off] = obj[off] + fus[off] + ra[off] * accR[i] + ba[off] * accB[i];
    }
}

extern "C" void kernel_launch(void* const* d_in, const int* in_sizes, int n_in,
                              void* d_out, int out_size) {
    const float* qe    = (const float*)d_in[0];
    const float* obj   = (const float*)d_in[1];
    const float* boxes = (const float*)d_in[2];
    const float* Wq    = (const float*)d_in[3];
    const float* Wo    = (const float*)d_in[4];
    const float* Wfa   = (const float*)d_in[5];
    const float* Wfb   = (const float*)d_in[6];
    const float* Wba   = (const float*)d_in[7];
    const float* Wbb   = (const float*)d_in[8];
    const float* W0    = (const float*)d_in[9];
    const float* b0    = (const float*)d_in[10];
    const float* W1    = (const float*)d_in[11];
    float* out = (float*)d_out;

    float *tmp1, *tmp2, *fusr, *ra, *rb, *ba, *bb;
    float *qer, *objr, *Wqr, *Wor, *Wfar, *Wfbr, *W0r, *scp, *attb;
    cudaGetSymbolAddress((void**)&tmp1, g_tmp1);
    cudaGetSymbolAddress((void**)&tmp2, g_tmp2);
    cudaGetSymbolAddress((void**)&fusr, g_fusr);
    cudaGetSymbolAddress((void**)&ra,   g_ra);
    cudaGetSymbolAddress((void**)&rb,   g_rb);
    cudaGetSymbolAddress((void**)&ba,   g_ba);
    cudaGetSymbolAddress((void**)&bb,   g_bb);
    cudaGetSymbolAddress((void**)&qer,  g_qer);
    cudaGetSymbolAddress((void**)&objr, g_objr);
    cudaGetSymbolAddress((void**)&Wqr,  g_Wqr);
    cudaGetSymbolAddress((void**)&Wor,  g_Wor);
    cudaGetSymbolAddress((void**)&Wfar, g_Wfar);
    cudaGetSymbolAddress((void**)&Wfbr, g_Wfbr);
    cudaGetSymbolAddress((void**)&W0r,  g_W0r);
    cudaGetSymbolAddress((void**)&scp,  g_scp);
    cudaGetSymbolAddress((void**)&attb, g_attb);

    cudaFuncSetAttribute(gemm_tc, cudaFuncAttributeMaxDynamicSharedMemorySize, 107520);
    cudaFuncSetAttribute(relattn_tc, cudaFuncAttributeMaxDynamicSharedMemorySize, 137984);

    const int nIO = ROWS * DF / 4;
    const int nW  = DF * DF / 4;
    const int nW0 = DF * DATT / 4;

    roundk<<<(nIO + 255) / 256, 256>>>(qe,  qer,  nIO);
    roundk<<<(nIO + 255) / 256, 256>>>(obj, objr, nIO);
    roundk<<<(nW  + 255) / 256, 256>>>(Wq,  Wqr,  nW);
    roundk<<<(nW  + 255) / 256, 256>>>(Wo,  Wor,  nW);
    roundk<<<(nW  + 255) / 256, 256>>>(Wfa, Wfar, nW);
    roundk<<<(nW  + 255) / 256, 256>>>(Wfb, Wfbr, nW);
    roundk<<<(nW0 + 255) / 256, 256>>>(W0,  W0r,  nW0);

    dim3 gg(DF / 256, ROWS / 128);     // (8, 18)
    gemm_tc<<<gg, 256, 107520>>>(qer,  Wqr, tmp1, ROWS, DF, DF);
    gemm_tc<<<gg, 256, 107520>>>(objr, Wor, tmp2, ROWS, DF, DF);
    fusek<<<(nIO + 255) / 256, 256>>>(tmp1, tmp2, fusr, nIO);  // tmp1=fused, fusr=rna(fused)
    gemm_tc<<<gg, 256, 107520>>>(fusr, Wfar, ra, ROWS, DF, DF);
    gemm_tc<<<gg, 256, 107520>>>(fusr, Wfbr, rb, ROWS, DF, DF);
    boxproj<<<(nIO + 255) / 256, 256>>>(boxes, Wba, Wbb, ba, bb);

    relattn_tc<<<dim3(2, 9, B_), 384, 137984>>>(ra, rb, ba, bb, W0r, b0, W1, scp);
    attk<<<(ROWS + 127) / 128, 128>>>(scp, attb);
    ehat_fin<<<dim3(16, B_), 256>>>(attb, ra, rb, ba, bb, obj, tmp1, out);
}

// round 8
// speedup vs baseline: 5.9065x; 1.0813x over previous
#include <cuda_runtime.h>
#include <math.h>
#include <stdint.h>

#define B_   64
#define N_   36
#define ROWS 2304      // B_*N_
#define DF   2048
#define DATT 512

// packed tile sizes (floats)
#define PA_CH 5120     // 128 x 40
#define PB_CH 8320     // 32 x 260
#define PR_CH 1440     // 36 x 40

// ---------------- scratch (static device buffers) ---------------------------
__device__ float g_tmp1[ROWS * DF];     // qe@Wq, then unrounded fused
__device__ float g_tmp2[ROWS * DF];     // obj@Wo
__device__ float g_ra[ROWS * DF];       // natural outputs
__device__ float g_rb[ROWS * DF];
__device__ float g_ba[ROWS * DF];
__device__ float g_bb[ROWS * DF];
__device__ float g_pqe[18 * 64 * PA_CH];   // packed rna A operands
__device__ float g_pobj[18 * 64 * PA_CH];
__device__ float g_pfus[18 * 64 * PA_CH];
__device__ float g_pWq[8 * 64 * PB_CH];    // packed rna weights
__device__ float g_pWo[8 * 64 * PB_CH];
__device__ float g_pWfa[8 * 64 * PB_CH];
__device__ float g_pWfb[8 * 64 * PB_CH];
__device__ float g_pW0[2 * 64 * PB_CH];
__device__ float g_pra[B_ * 64 * PR_CH];   // packed raw relattn operands
__device__ float g_prb[B_ * 64 * PR_CH];
__device__ float g_pba[B_ * 64 * PR_CH];
__device__ float g_pbb[B_ * 64 * PR_CH];
__device__ float g_scp[2 * 9 * B_ * 144];
__device__ float g_attb[ROWS * N_];

// ---------------- PTX helpers ------------------------------------------------
__device__ __forceinline__ float tf32r(float x) {
    uint32_t u; asm("cvt.rna.tf32.f32 %0, %1;" : "=r"(u) : "f"(x));
    return __uint_as_float(u);
}
__device__ __forceinline__ uint32_t smem_u32(const void* p) {
    uint32_t a;
    asm("{ .reg .u64 t; cvta.to.shared.u64 t, %1; cvt.u32.u64 %0, t; }" : "=r"(a) : "l"(p));
    return a;
}
__device__ __forceinline__ void mma8(float* d, const uint32_t* a, const uint32_t* b) {
    asm volatile("mma.sync.aligned.m16n8k8.row.col.f32.tf32.tf32.f32 "
                 "{%0,%1,%2,%3}, {%4,%5,%6,%7}, {%8,%9}, {%0,%1,%2,%3};"
                 : "+f"(d[0]), "+f"(d[1]), "+f"(d[2]), "+f"(d[3])
                 : "r"(a[0]), "r"(a[1]), "r"(a[2]), "r"(a[3]),
                   "r"(b[0]), "r"(b[1]));
}
__device__ __forceinline__ void blkcp(uint32_t dst, const void* src,
                                      uint32_t bytes, uint32_t bar) {
    asm volatile("cp.async.bulk.shared::cta.global.mbarrier::complete_tx::bytes "
                 "[%0], [%1], %2, [%3];"
                 :: "r"(dst), "l"(src), "r"(bytes), "r"(bar) : "memory");
}
#define MBAR_INIT(a, n) \
    asm volatile("mbarrier.init.shared.b64 [%0], %1;" :: "r"(a), "r"(n) : "memory")
#define MBAR_EXPECT(a, n) \
    asm volatile("mbarrier.arrive.expect_tx.shared.b64 _, [%0], %1;" :: "r"(a), "r"(n) : "memory")
#define MBAR_WAIT(a, ph) do {                                                   \
    uint32_t _m = (a), _p = (ph), _d;                                           \
    asm volatile("{\n\t.reg .pred p;\n\t"                                       \
        "mbarrier.try_wait.parity.acquire.cta.shared::cta.b64 p, [%1], %2;\n\t" \
        "selp.b32 %0, 1, 0, p;\n\t}" : "=r"(_d) : "r"(_m), "r"(_p) : "memory"); \
    if (!_d) {                                                                  \
        asm volatile("{\n\t.reg .pred P;\n\t"                                   \
            "WL_%=:\n\t"                                                        \
            "mbarrier.try_wait.parity.acquire.cta.shared::cta.b64 P, [%0], %1, 0x989680;\n\t" \
            "@P bra.uni WD_%=;\n\t"                                             \
            "bra.uni WL_%=;\n\t"                                                \
            "WD_%=:\n\t}" :: "r"(_m), "r"(_p) : "memory");                      \
    } } while (0)

// ---------------- packing / elementwise kernels ------------------------------
// A natural [2304][2048] -> packed rna [tile18][chunk64][128][40]
__global__ void packA(const float* __restrict__ in, float* __restrict__ out) {
    int i = blockIdx.x * blockDim.x + threadIdx.x;
    if (i >= ROWS * DF / 4) return;
    int e = i * 4;
    int r = e / DF, c = e % DF;
    float4 v = *(const float4*)&in[e];
    v.x = tf32r(v.x); v.y = tf32r(v.y); v.z = tf32r(v.z); v.w = tf32r(v.w);
    size_t o = ((size_t)((r >> 7) * 64 + (c >> 5)) * 128 + (r & 127)) * 40 + (c & 31);
    *(float4*)&out[o] = v;
}

// W natural [2048][2048] -> packed rna [ntile8][chunk64][32][260]
__global__ void packW(const float* __restrict__ in, float* __restrict__ out) {
    int i = blockIdx.x * blockDim.x + threadIdx.x;
    if (i >= DF * DF / 4) return;
    int e = i * 4;
    int k = e / DF, n = e % DF;
    float4 v = *(const float4*)&in[e];
    v.x = tf32r(v.x); v.y = tf32r(v.y); v.z = tf32r(v.z); v.w = tf32r(v.w);
    size_t o = ((size_t)((n >> 8) * 64 + (k >> 5)) * 32 + (k & 31)) * 260 + (n & 255);
    *(float4*)&out[o] = v;
}

// W0 natural [2048][512] -> packed rna [slice2][chunk64][32][260]
__global__ void packW0(const float* __restrict__ in, float* __restrict__ out) {
    int i = blockIdx.x * blockDim.x + threadIdx.x;
    if (i >= DF * DATT / 4) return;
    int e = i * 4;
    int k = e / DATT, n = e % DATT;
    float4 v = *(const float4*)&in[e];
    v.x = tf32r(v.x); v.y = tf32r(v.y); v.z = tf32r(v.z); v.w = tf32r(v.w);
    size_t o = ((size_t)((n >> 8) * 64 + (k >> 5)) * 32 + (k & 31)) * 260 + (n & 255);
    *(float4*)&out[o] = v;
}

// natural [2304][2048] -> packed RAW [b64][chunk64][36][40]
__global__ void packRB(const float* __restrict__ in, float* __restrict__ out) {
    int i = blockIdx.x * blockDim.x + threadIdx.x;
    if (i >= ROWS * DF / 4) return;
    int e = i * 4;
    int r = e / DF, c = e % DF;
    int b = r / N_, j = r - b * N_;
    float4 v = *(const float4*)&in[e];
    size_t o = ((size_t)(b * 64 + (c >> 5)) * 36 + j) * 40 + (c & 31);
    *(float4*)&out[o] = v;
}

// tmp1 = tmp1*tmp2 (natural, residual); packed rna product -> pfus
__global__ void fusek(float* __restrict__ a, const float* __restrict__ b,
                      float* __restrict__ pk) {
    int i = blockIdx.x * blockDim.x + threadIdx.x;
    if (i >= ROWS * DF / 4) return;
    int e = i * 4;
    int r = e / DF, c = e % DF;
    float4 x = *(float4*)&a[e];
    float4 y = *(const float4*)&b[e];
    x.x *= y.x; x.y *= y.y; x.z *= y.z; x.w *= y.w;
    *(float4*)&a[e] = x;
    float4 v;
    v.x = tf32r(x.x); v.y = tf32r(x.y); v.z = tf32r(x.z); v.w = tf32r(x.w);
    size_t o = ((size_t)((r >> 7) * 64 + (c >> 5)) * 128 + (r & 127)) * 40 + (c & 31);
    *(float4*)&pk[o] = v;
}

// ba = boxes @ Wba, bb = boxes @ Wbb  (K = 4)
__global__ void boxproj(const float* __restrict__ boxes,
                        const float* __restrict__ Wba, const float* __restrict__ Wbb,
                        float* __restrict__ ba, float* __restrict__ bb) {
    int idx = blockIdx.x * blockDim.x + threadIdx.x;
    if (idx >= ROWS * (DF / 4)) return;
    int r  = idx / (DF / 4);
    int dq = (idx % (DF / 4)) * 4;
    float4 bx = *(const float4*)&boxes[r * 4];
    float c[4] = {bx.x, bx.y, bx.z, bx.w};
    float4 sa = make_float4(0.f, 0.f, 0.f, 0.f);
    float4 sb = make_float4(0.f, 0.f, 0.f, 0.f);
#pragma unroll
    for (int cc = 0; cc < 4; cc++) {
        float4 wa = *(const float4*)&Wba[cc * DF + dq];
        float4 wb = *(const float4*)&Wbb[cc * DF + dq];
        sa.x += c[cc] * wa.x; sa.y += c[cc] * wa.y; sa.z += c[cc] * wa.z; sa.w += c[cc] * wa.w;
        sb.x += c[cc] * wb.x; sb.y += c[cc] * wb.y; sb.z += c[cc] * wb.z; sb.w += c[cc] * wb.w;
    }
    *(float4*)&ba[(size_t)r * DF + dq] = sa;
    *(float4*)&bb[(size_t)r * DF + dq] = sb;
}

// ---------------------------------------------------------------------------
// tf32 mma.sync GEMM, bulk-copy staged from packed operands.
// CTA 128x256, 3-stage pipeline, K-chunk 32, 8 warps of 64x64.
// smem floats: bars[0..15], As@16 (3x5120), Bs@15376 (3x8320).
// ---------------------------------------------------------------------------
#define G_SMEM (40336 * 4)
__global__ __launch_bounds__(256)
void gemm_tc3(const float* __restrict__ pa, const float* __restrict__ pb,
              float* __restrict__ C) {
    extern __shared__ float smf[];
    uint32_t smb = smem_u32(smf);
    const int tid = threadIdx.x, lane = tid & 31, wid = tid >> 5;
    const int cc = lane & 3, q = lane >> 2;
    const int wm = (wid >> 2) * 64, wn = (wid & 3) * 64;
    const int tileM = blockIdx.y, tileN = blockIdx.x;
    float* As = smf + 16;
    float* Bs = smf + 16 + 3 * PA_CH;

    if (tid == 0) {
#pragma unroll
        for (int s = 0; s < 3; s++) MBAR_INIT(smb + 8 * s, 1);
    }
    __syncthreads();

    auto issue = [&](int kc) {
        int s = kc % 3;
        uint32_t bar = smb + 8 * s;
        MBAR_EXPECT(bar, 53760);
        blkcp(smb + (16 + s * PA_CH) * 4,
              pa + ((size_t)tileM * 64 + kc) * PA_CH, 20480, bar);
        blkcp(smb + (16 + 3 * PA_CH + s * PB_CH) * 4,
              pb + ((size_t)tileN * 64 + kc) * PB_CH, 33280, bar);
    };
    if (tid == 0) { issue(0); issue(1); issue(2); }

    float acc[4][8][4];
#pragma unroll
    for (int i = 0; i < 4; i++)
#pragma unroll
        for (int j = 0; j < 8; j++)
#pragma unroll
            for (int p = 0; p < 4; p++) acc[i][j][p] = 0.f;

    for (int kc = 0; kc < 64; kc++) {
        int s = kc % 3;
        MBAR_WAIT(smb + 8 * s, (kc / 3) & 1);
        const float* Ab = As + s * PA_CH;
        const float* Bb = Bs + s * PB_CH;
#pragma unroll
        for (int kb = 0; kb < 32; kb += 8) {
            uint32_t af[4][4], bf[8][2];
#pragma unroll
            for (int mf = 0; mf < 4; mf++) {
                int r = wm + mf * 16 + q;
                float2 lo = *(const float2*)&Ab[r * 40 + kb + 2 * cc];
                float2 hi = *(const float2*)&Ab[(r + 8) * 40 + kb + 2 * cc];
                af[mf][0] = __float_as_uint(lo.x);
                af[mf][1] = __float_as_uint(hi.x);
                af[mf][2] = __float_as_uint(lo.y);
                af[mf][3] = __float_as_uint(hi.y);
            }
#pragma unroll
            for (int nf = 0; nf < 8; nf++) {
                int ci = (kb + 2 * cc) * 260 + wn + nf * 8 + q;
                bf[nf][0] = __float_as_uint(Bb[ci]);
                bf[nf][1] = __float_as_uint(Bb[ci + 260]);
            }
#pragma unroll
            for (int mf = 0; mf < 4; mf++)
#pragma unroll
                for (int nf = 0; nf < 8; nf++)
                    mma8(acc[mf][nf], af[mf], bf[nf]);
        }
        __syncthreads();
        if (tid == 0 && kc + 3 < 64) issue(kc + 3);
    }

    const int m0 = tileM * 128, n0 = tileN * 256;
#pragma unroll
    for (int mf = 0; mf < 4; mf++) {
        int r0 = m0 + wm + mf * 16 + q;
#pragma unroll
        for (int nf = 0; nf < 8; nf++) {
            int c = n0 + wn + nf * 8 + 2 * cc;
            *(float2*)&C[(size_t)r0 * DF + c] = make_float2(acc[mf][nf][0], acc[mf][nf][1]);
            *(float2*)&C[(size_t)(r0 + 8) * DF + c] = make_float2(acc[mf][nf][2], acc[mf][nf][3]);
        }
    }
}

// ---------------------------------------------------------------------------
// Relation-attention scores: bulk-staged operands, G computed IN REGISTERS
// (rna) at fragment build — no Gs smem, no buildG pass.
// Grid (slice2, ig9, b64), 384 threads, 12 warps (3M x 4N), warp 48x64.
// smem floats: bars[0..15], Ws@16 (3x8320), rbS@24976 (3x1440),
//              bbS@29296, raS@33616 (3x160), baS@34096, red@34576 (576).
// ---------------------------------------------------------------------------
#define R_SMEM (35152 * 4)
__global__ __launch_bounds__(384)
void relattn_blk(const float* __restrict__ pra, const float* __restrict__ prb,
                 const float* __restrict__ pba, const float* __restrict__ pbb,
                 const float* __restrict__ pw0, const float* __restrict__ b0,
                 const float* __restrict__ W1, float* __restrict__ scp) {
    extern __shared__ float smf[];
    uint32_t smb = smem_u32(smf);
    float* Ws  = smf + 16;
    float* rbS = smf + 24976;
    float* bbS = smf + 29296;
    float* raS = smf + 33616;
    float* baS = smf + 34096;
    float* red = smf + 34576;
    const int tid = threadIdx.x, lane = tid & 31, wid = tid >> 5;
    const int cc = lane & 3, q = lane >> 2;
    const int wm = (wid >> 2) * 48, wn = (wid & 3) * 64;
    const int slice = blockIdx.x, ig = blockIdx.y, b = blockIdx.z;

    if (tid == 0) {
#pragma unroll
        for (int s = 0; s < 3; s++) MBAR_INIT(smb + 8 * s, 1);
    }
    __syncthreads();

    // per-thread row offsets (constant across chunks)
    int oRBl[3], oRBh[3], oRAl[3], oRAh[3];
#pragma unroll
    for (int mf = 0; mf < 3; mf++) {
        int rl = wm + mf * 16 + q, rh = rl + 8;
        oRBl[mf] = (rl % 36) * 40; oRAl[mf] = (rl / 36) * 40;
        oRBh[mf] = (rh % 36) * 40; oRAh[mf] = (rh / 36) * 40;
    }

    auto issue = [&](int kc) {
        int s = kc % 3;
        uint32_t bar = smb + 8 * s;
        MBAR_EXPECT(bar, 46080);
        blkcp(smb + (16 + s * PB_CH) * 4,
              pw0 + ((size_t)slice * 64 + kc) * PB_CH, 33280, bar);
        size_t rbase = ((size_t)b * 64 + kc) * PR_CH;
        blkcp(smb + (24976 + s * PR_CH) * 4, prb + rbase, 5760, bar);
        blkcp(smb + (29296 + s * PR_CH) * 4, pbb + rbase, 5760, bar);
        blkcp(smb + (33616 + s * 160) * 4, pra + rbase + ig * 160, 640, bar);
        blkcp(smb + (34096 + s * 160) * 4, pba + rbase + ig * 160, 640, bar);
    };
    if (tid == 0) { issue(0); issue(1); issue(2); }

    float acc[3][8][4];
#pragma unroll
    for (int i = 0; i < 3; i++)
#pragma unroll
        for (int j = 0; j < 8; j++)
#pragma unroll
            for (int p = 0; p < 4; p++) acc[i][j][p] = 0.f;

    for (int kc = 0; kc < 64; kc++) {
        int s = kc % 3;
        MBAR_WAIT(smb + 8 * s, (kc / 3) & 1);
        const float* Wb = Ws + s * PB_CH;
        const float* rs = rbS + s * PR_CH;
        const float* bs = bbS + s * PR_CH;
        const float* us = raS + s * 160;
        const float* vs = baS + s * 160;
#pragma unroll
        for (int kb = 0; kb < 32; kb += 8) {
            const int k = kb + 2 * cc;
            uint32_t bf[8][2];
#pragma unroll
            for (int nf = 0; nf < 8; nf++) {
                int ci = k * 260 + wn + nf * 8 + q;
                bf[nf][0] = __float_as_uint(Wb[ci]);
                bf[nf][1] = __float_as_uint(Wb[ci + 260]);
            }
#pragma unroll
            for (int mf = 0; mf < 3; mf++) {
                float2 rv0 = *(const float2*)&rs[oRBl[mf] + k];
                float2 bv0 = *(const float2*)&bs[oRBl[mf] + k];
                float2 u0  = *(const float2*)&us[oRAl[mf] + k];
                float2 v0  = *(const float2*)&vs[oRAl[mf] + k];
                float2 rv1 = *(const float2*)&rs[oRBh[mf] + k];
                float2 bv1 = *(const float2*)&bs[oRBh[mf] + k];
                float2 u1  = *(const float2*)&us[oRAh[mf] + k];
                float2 v1  = *(const float2*)&vs[oRAh[mf] + k];
                uint32_t af[4];
                af[0] = __float_as_uint(tf32r(fmaf(v0.x, bv0.x, u0.x * rv0.x)));
                af[1] = __float_as_uint(tf32r(fmaf(v1.x, bv1.x, u1.x * rv1.x)));
                af[2] = __float_as_uint(tf32r(fmaf(v0.y, bv0.y, u0.y * rv0.y)));
                af[3] = __float_as_uint(tf32r(fmaf(v1.y, bv1.y, u1.y * rv1.y)));
#pragma unroll
                for (int nf = 0; nf < 8; nf++)
                    mma8(acc[mf][nf], af, bf[nf]);
            }
        }
        __syncthreads();
        if (tid == 0 && kc + 3 < 64) issue(kc + 3);
    }

    // epilogue: partial scores over this 256-col slice (deterministic order)
    const float* b0g = b0 + slice * 256;
    const float* W1g = W1 + slice * 256;
#pragma unroll
    for (int mf = 0; mf < 3; mf++) {
        float s0 = 0.f, s1 = 0.f;
#pragma unroll
        for (int nf = 0; nf < 8; nf++) {
            int c0 = wn + nf * 8 + 2 * cc;
            float w0 = W1g[c0],     e0 = b0g[c0];
            float w1 = W1g[c0 + 1], e1 = b0g[c0 + 1];
            s0 += w0 * tanhf(acc[mf][nf][0] + e0) + w1 * tanhf(acc[mf][nf][1] + e1);
            s1 += w0 * tanhf(acc[mf][nf][2] + e0) + w1 * tanhf(acc[mf][nf][3] + e1);
        }
        s0 += __shfl_xor_sync(0xffffffffu, s0, 1);
        s0 += __shfl_xor_sync(0xffffffffu, s0, 2);
        s1 += __shfl_xor_sync(0xffffffffu, s1, 1);
        s1 += __shfl_xor_sync(0xffffffffu, s1, 2);
        if (cc == 0) {
            int r = wm + mf * 16 + q;
            red[r * 4 + (wid & 3)]       = s0;
            red[(r + 8) * 4 + (wid & 3)] = s1;
        }
    }
    __syncthreads();
    if (tid < 144) {
        float tot = red[tid * 4] + red[tid * 4 + 1] + red[tid * 4 + 2] + red[tid * 4 + 3];
        scp[(((size_t)slice * B_ + b) * 9 + ig) * 144 + tid] = tot;
    }
}

// softmax over j for each (b,i)
__global__ void attk(const float* __restrict__ scp, float* __restrict__ att) {
    int bi = blockIdx.x * blockDim.x + threadIdx.x;
    if (bi >= ROWS) return;
    int b = bi / N_, i = bi - b * N_;
    int ig = i >> 2, il = i & 3;
    float sc[N_];
#pragma unroll 4
    for (int j = 0; j < N_; j++) {
        sc[j] = scp[(((size_t)b) * 9 + ig) * 144 + il * 36 + j]
              + scp[(((size_t)B_ + b) * 9 + ig) * 144 + il * 36 + j];
    }
    float m = sc[0];
    for (int j = 1; j < N_; j++) m = fmaxf(m, sc[j]);
    float sum = 0.f;
    for (int j = 0; j < N_; j++) { sc[j] = expf(sc[j] - m); sum += sc[j]; }
    float inv = 1.f / sum;
    for (int j = 0; j < N_; j++) att[(size_t)bi * N_ + j] = sc[j] * inv;
}

// out = obj + fused + ra.*(att@rb) + ba.*(att@bb)
__global__ __launch_bounds__(256)
void ehat_fin(const float* __restrict__ att,
              const float* __restrict__ ra, const float* __restrict__ rb,
              const float* __restrict__ ba, const float* __restrict__ bb,
              const float* __restrict__ obj, const float* __restrict__ fus,
              float* __restrict__ out) {
    __shared__ float att_s[N_][N_ + 1];
    const int tid = threadIdx.x;
    const int b = blockIdx.y, d0 = blockIdx.x * 128;
    const int d = tid & 127, half = tid >> 7;
    for (int idx = tid; idx < N_ * N_; idx += 256)
        att_s[idx / N_][idx % N_] = att[(size_t)(b * N_ + idx / N_) * N_ + idx % N_];
    __syncthreads();
    const float* rbB = rb + (size_t)b * N_ * DF + d0 + d;
    const float* bbB = bb + (size_t)b * N_ * DF + d0 + d;
    float accR[18], accB[18];
#pragma unroll
    for (int i = 0; i < 18; i++) { accR[i] = 0.f; accB[i] = 0.f; }
    for (int j = 0; j < N_; j++) {
        float rv = rbB[(size_t)j * DF];
        float bv = bbB[(size_t)j * DF];
#pragma unroll
        for (int i = 0; i < 18; i++) {
            float a = att_s[half * 18 + i][j];
            accR[i] += a * rv;
            accB[i] += a * bv;
        }
    }
#pragma unroll
    for (int i = 0; i < 18; i++) {
        size_t row = (size_t)b * N_ + half * 18 + i;
        size_t off = row * DF + d0 + d;
        out[off] = obj[off] + fus[off] + ra[off] * accR[i] + ba[off] * accB[i];
    }
}

extern "C" void kernel_launch(void* const* d_in, const int* in_sizes, int n_in,
                              void* d_out, int out_size) {
    const float* qe    = (const float*)d_in[0];
    const float* obj   = (const float*)d_in[1];
    const float* boxes = (const float*)d_in[2];
    const float* Wq    = (const float*)d_in[3];
    const float* Wo    = (const float*)d_in[4];
    const float* Wfa   = (const float*)d_in[5];
    const float* Wfb   = (const float*)d_in[6];
    const float* Wba   = (const float*)d_in[7];
    const float* Wbb   = (const float*)d_in[8];
    const float* W0    = (const float*)d_in[9];
    const float* b0    = (const float*)d_in[10];
    const float* W1    = (const float*)d_in[11];
    float* out = (float*)d_out;

    float *tmp1, *tmp2, *ra, *rb, *ba, *bb;
    float *pqe, *pobj, *pfus, *pWq, *pWo, *pWfa, *pWfb, *pW0;
    float *pra, *prb, *pba, *pbb, *scp, *attb;
    cudaGetSymbolAddress((void**)&tmp1, g_tmp1);
    cudaGetSymbolAddress((void**)&tmp2, g_tmp2);
    cudaGetSymbolAddress((void**)&ra,   g_ra);
    cudaGetSymbolAddress((void**)&rb,   g_rb);
    cudaGetSymbolAddress((void**)&ba,   g_ba);
    cudaGetSymbolAddress((void**)&bb,   g_bb);
    cudaGetSymbolAddress((void**)&pqe,  g_pqe);
    cudaGetSymbolAddress((void**)&pobj, g_pobj);
    cudaGetSymbolAddress((void**)&pfus, g_pfus);
    cudaGetSymbolAddress((void**)&pWq,  g_pWq);
    cudaGetSymbolAddress((void**)&pWo,  g_pWo);
    cudaGetSymbolAddress((void**)&pWfa, g_pWfa);
    cudaGetSymbolAddress((void**)&pWfb, g_pWfb);
    cudaGetSymbolAddress((void**)&pW0,  g_pW0);
    cudaGetSymbolAddress((void**)&pra,  g_pra);
    cudaGetSymbolAddress((void**)&prb,  g_prb);
    cudaGetSymbolAddress((void**)&pba,  g_pba);
    cudaGetSymbolAddress((void**)&pbb,  g_pbb);
    cudaGetSymbolAddress((void**)&scp,  g_scp);
    cudaGetSymbolAddress((void**)&attb, g_attb);

    cudaFuncSetAttribute(gemm_tc3, cudaFuncAttributeMaxDynamicSharedMemorySize, G_SMEM);
    cudaFuncSetAttribute(relattn_blk, cudaFuncAttributeMaxDynamicSharedMemorySize, R_SMEM);

    const int nIO = ROWS * DF / 4;      // 1179648
    const int nW  = DF * DF / 4;        // 1048576
    const int nW0 = DF * DATT / 4;      // 262144

    packW<<<(nW + 255) / 256, 256>>>(Wq,  pWq);
    packW<<<(nW + 255) / 256, 256>>>(Wo,  pWo);
    packW<<<(nW + 255) / 256, 256>>>(Wfa, pWfa);
    packW<<<(nW + 255) / 256, 256>>>(Wfb, pWfb);
    packW0<<<(nW0 + 255) / 256, 256>>>(W0, pW0);
    packA<<<(nIO + 255) / 256, 256>>>(qe,  pqe);
    packA<<<(nIO + 255) / 256, 256>>>(obj, pobj);

    dim3 gg(DF / 256, ROWS / 128);      // (8, 18)
    gemm_tc3<<<gg, 256, G_SMEM>>>(pqe,  pWq, tmp1);
    gemm_tc3<<<gg, 256, G_SMEM>>>(pobj, pWo, tmp2);
    fusek<<<(nIO + 255) / 256, 256>>>(tmp1, tmp2, pfus);
    gemm_tc3<<<gg, 256, G_SMEM>>>(pfus, pWfa, ra);
    gemm_tc3<<<gg, 256, G_SMEM>>>(pfus, pWfb, rb);
    boxproj<<<(nIO + 255) / 256, 256>>>(boxes, Wba, Wbb, ba, bb);

    packRB<<<(nIO + 255) / 256, 256>>>(ra, pra);
    packRB<<<(nIO + 255) / 256, 256>>>(rb, prb);
    packRB<<<(nIO + 255) / 256, 256>>>(ba, pba);
    packRB<<<(nIO + 255) / 256, 256>>>(bb, pbb);

    relattn_blk<<<dim3(2, 9, B_), 384, R_SMEM>>>(pra, prb, pba, pbb, pW0, b0, W1, scp);
    attk<<<(ROWS + 127) / 128, 128>>>(scp, attb);
    ehat_fin<<<dim3(16, B_), 256>>>(attb, ra, rb, ba, bb, obj, tmp1, out);
}